// round 4
// baseline (speedup 1.0000x reference)
#include <cuda_runtime.h>
#include <cuda_bf16.h>

#define NN    6000
#define DEG   16
#define MM    17      // DEG+1
#define NT    16
#define MT    10
#define MTP   12      // padded row (floats)
#define NF    128
#define NKT   (NT*MT) // 160
#define REGc  0.1f

// ---------------- device scratch (no cudaMalloc allowed) ----------------
__device__ int      g_nbrs[NN * MM];
__device__ unsigned g_B[NN * MM];
__device__ unsigned g_mask[NN * MM];
__device__ float    g_f2n[NKT];
__device__ float    g_consts[3];     // cA = 2a/REG, cY = 4a/REG, cM = (1-a)/REG
__device__ float    g_D[NN * NKT];   // cM*(f2n[kt] - 2 * x[u] . F2[kt])

// packed f32x2 dot over 10 elements (both operands 16B-aligned smem rows)
__device__ __forceinline__ float dot10p(const float* __restrict__ a,
                                        const float* __restrict__ b) {
    const ulonglong2* A = (const ulonglong2*)a;
    const ulonglong2* B = (const ulonglong2*)b;
    ulonglong2 A0 = A[0], A1 = A[1];
    ulonglong2 B0 = B[0], B1 = B[1];
    unsigned long long a2 = *(const unsigned long long*)(a + 8);
    unsigned long long b2 = *(const unsigned long long*)(b + 8);
    unsigned long long acc;
    asm("mul.rn.f32x2 %0, %1, %2;"     : "=l"(acc) : "l"(A0.x), "l"(B0.x));
    asm("fma.rn.f32x2 %0, %1, %2, %0;" : "+l"(acc) : "l"(A0.y), "l"(B0.y));
    asm("fma.rn.f32x2 %0, %1, %2, %0;" : "+l"(acc) : "l"(A1.x), "l"(B1.x));
    asm("fma.rn.f32x2 %0, %1, %2, %0;" : "+l"(acc) : "l"(A1.y), "l"(B1.y));
    asm("fma.rn.f32x2 %0, %1, %2, %0;" : "+l"(acc) : "l"(a2),   "l"(b2));
    unsigned lo, hi;
    asm("mov.b64 {%0,%1}, %2;" : "=r"(lo), "=r"(hi) : "l"(acc));
    return __uint_as_float(lo) + __uint_as_float(hi);
}

// packed dot: smem row vs 5 register-packed f32x2 values
__device__ __forceinline__ float dot10r(const float* __restrict__ a,
                                        unsigned long long b0, unsigned long long b1,
                                        unsigned long long b2, unsigned long long b3,
                                        unsigned long long b4) {
    const ulonglong2* A = (const ulonglong2*)a;
    ulonglong2 A0 = A[0], A1 = A[1];
    unsigned long long a2 = *(const unsigned long long*)(a + 8);
    unsigned long long acc;
    asm("mul.rn.f32x2 %0, %1, %2;"     : "=l"(acc) : "l"(A0.x), "l"(b0));
    asm("fma.rn.f32x2 %0, %1, %2, %0;" : "+l"(acc) : "l"(A0.y), "l"(b1));
    asm("fma.rn.f32x2 %0, %1, %2, %0;" : "+l"(acc) : "l"(A1.x), "l"(b2));
    asm("fma.rn.f32x2 %0, %1, %2, %0;" : "+l"(acc) : "l"(A1.y), "l"(b3));
    asm("fma.rn.f32x2 %0, %1, %2, %0;" : "+l"(acc) : "l"(a2),   "l"(b4));
    unsigned lo, hi;
    asm("mov.b64 {%0,%1}, %2;" : "=r"(lo), "=r"(hi) : "l"(acc));
    return __uint_as_float(lo) + __uint_as_float(hi);
}

__device__ __forceinline__ unsigned long long pack2(float x, float y) {
    unsigned long long r;
    asm("mov.b64 %0, {%1, %2};" : "=l"(r) : "r"(__float_as_uint(x)), "r"(__float_as_uint(y)));
    return r;
}

// ---------------- setup: constants + |F2|^2 ----------------
__global__ void k_setup(const float* __restrict__ alpha0,
                        const float* __restrict__ F2) {
    int tid = threadIdx.x;
    if (tid == 0) {
        float a0 = alpha0[0];
        float alpha = 1.0f / (1.0f + __expf(-a0));
        g_consts[0] = 2.0f * alpha / REGc;
        g_consts[1] = 4.0f * alpha / REGc;
        g_consts[2] = (1.0f - alpha) / REGc;
    }
    for (int idx = tid; idx < NKT; idx += blockDim.x) {
        const float* row = F2 + (size_t)idx * NF;
        float s = 0.f;
        #pragma unroll 8
        for (int f = 0; f < NF; f++) { float v = row[f]; s += v * v; }
        g_f2n[idx] = s;
    }
}

// ---------------- GEMM: D = cM*(f2n - 2 * x @ F2^T) ----------------
__global__ void __launch_bounds__(256, 4)
k_gemm(const float* __restrict__ x, const float* __restrict__ F2) {
    __shared__ float sX[32][65];
    __shared__ float sF[32][161];

    const int tid = threadIdx.x;
    const int tr  = tid & 15;
    const int tc  = tid >> 4;
    const int r0  = blockIdx.x * 64;

    float acc[4][10];
    #pragma unroll
    for (int i = 0; i < 4; i++)
        #pragma unroll
        for (int j = 0; j < 10; j++) acc[i][j] = 0.f;

    for (int k0 = 0; k0 < NF; k0 += 32) {
        __syncthreads();
        for (int idx = tid; idx < 512; idx += 256) {
            int rr = idx >> 3, c4 = idx & 7;
            int gr = r0 + rr;
            float4 v = (gr < NN) ? __ldg((const float4*)(x + (size_t)gr * NF + k0) + c4)
                                 : make_float4(0.f, 0.f, 0.f, 0.f);
            sX[c4*4+0][rr] = v.x; sX[c4*4+1][rr] = v.y;
            sX[c4*4+2][rr] = v.z; sX[c4*4+3][rr] = v.w;
        }
        for (int idx = tid; idx < 1280; idx += 256) {
            int cc = idx >> 3, c4 = idx & 7;
            float4 v = __ldg((const float4*)(F2 + (size_t)cc * NF + k0) + c4);
            sF[c4*4+0][cc] = v.x; sF[c4*4+1][cc] = v.y;
            sF[c4*4+2][cc] = v.z; sF[c4*4+3][cc] = v.w;
        }
        __syncthreads();

        #pragma unroll 4
        for (int kk = 0; kk < 32; kk++) {
            float b[10];
            #pragma unroll
            for (int j = 0; j < 10; j++) b[j] = sF[kk][tc*10 + j];
            #pragma unroll
            for (int i = 0; i < 4; i++) {
                float a = sX[kk][tr + 16*i];
                #pragma unroll
                for (int j = 0; j < 10; j++) acc[i][j] = fmaf(a, b[j], acc[i][j]);
            }
        }
    }

    const float cM = g_consts[2];
    float f2c[10];
    #pragma unroll
    for (int j = 0; j < 10; j++) f2c[j] = g_f2n[tc*10 + j];
    #pragma unroll
    for (int i = 0; i < 4; i++) {
        int r = r0 + tr + 16*i;
        if (r < NN) {
            float* drow = g_D + (size_t)r * NKT + tc*10;
            #pragma unroll
            for (int j = 0; j < 10; j++)
                drow[j] = cM * (f2c[j] - 2.0f * acc[i][j]);
        }
    }
}

// ---------------- build directed-adjacency bitmasks B ----------------
__global__ void k_buildB(const int* __restrict__ dst) {
    int gid = blockIdx.x * blockDim.x + threadIdx.x;
    if (gid >= NN * MM) return;
    int n = gid / MM;
    int i = gid - n * MM;
    const int* dstn = dst + (size_t)n * DEG;
    int u = (i == 0) ? n : dstn[i - 1];
    g_nbrs[gid] = u;

    const int* dstu = dst + (size_t)u * DEG;
    int du[DEG];
    #pragma unroll
    for (int e = 0; e < DEG; e++) du[e] = dstu[e];
    int dn[DEG];
    #pragma unroll
    for (int e = 0; e < DEG; e++) dn[e] = dstn[e];

    unsigned bits = 0;
    #pragma unroll
    for (int j = 0; j < MM; j++) {
        int v = (j == 0) ? n : dn[j - 1];
        bool hit = false;
        #pragma unroll
        for (int e = 0; e < DEG; e++) hit |= (du[e] == v);
        bits |= (unsigned)hit << j;
    }
    g_B[gid] = bits;
}

// ---------------- symmetrize: C1 = B | B^T ----------------
__global__ void k_sym() {
    int gid = blockIdx.x * blockDim.x + threadIdx.x;
    if (gid >= NN * MM) return;
    int n = gid / MM;
    int i = gid - n * MM;
    unsigned mk = g_B[gid];
    const unsigned* Bn = g_B + n * MM;
    #pragma unroll
    for (int j = 0; j < MM; j++)
        mk |= ((Bn[j] >> i) & 1u) << j;
    g_mask[gid] = mk;
}

// ---------------- main: 10 mirror-descent iters + q ----------------
__global__ void __launch_bounds__(272, 7)
k_main(const float* __restrict__ C2g, float* __restrict__ out) {
    __shared__ __align__(16) float sT [NT][MM][MTP];
    __shared__ __align__(16) float sC2[NT][MT][MTP];
    __shared__ __align__(16) float sq [NT][MTP];
    __shared__ __align__(16) float sU [NT][MTP];   // cY*W0 - cA*constC2   (m>=1)
    __shared__ __align__(16) float sU0[NT][MTP];   // cY*(Zq + c00w*W0) - cA*constC2 (m==0)
    __shared__ float sc00[NT];

    const int tid = threadIdx.x;
    const int n   = blockIdx.x;
    const int k   = tid / MM;
    const int m   = tid - k * MM;

    // cooperative load of C2 into padded smem
    for (int idx = tid; idx < NT * MT * MTP; idx += 272) {
        int kk = idx / (MT * MTP);
        int r  = idx - kk * MT * MTP;
        int s  = r / MTP;
        int t  = r - s * MTP;
        ((float*)sC2)[idx] = (t < MT) ? C2g[(kk * MT + s) * MT + t] : 0.f;
    }

    const float cA = g_consts[0];
    const float cY = g_consts[1];

    // per-thread t-varying cost term (t-constant parts cancel in softmax)
    const int u = g_nbrs[n * MM + m];
    float basec[MT];
    {
        const float2* drow = (const float2*)(g_D + (size_t)u * NKT + k * MT);
        #pragma unroll
        for (int h = 0; h < 5; h++) {
            float2 v = __ldg(drow + h);
            basec[2*h]   = v.x;
            basec[2*h+1] = v.y;
        }
    }

    const unsigned mask = g_mask[n * MM + m];
    const unsigned resmask = (m == 0) ? 0u : (mask & ~1u);
    if (m == 0) sc00[k] = (mask & 1u) ? 0.f : -1.f;   // C1[0,0] - 1

    float lt[MT];
    #pragma unroll
    for (int t = 0; t < MT; t++) lt[t] = 0.f;
    float e[MT];
    float w0own = 0.f;

    __syncthreads();

    #pragma unroll 1
    for (int it = 0; it < 10; it++) {
        // softmax row in registers; T = p * softmax
        float mx = lt[0];
        #pragma unroll
        for (int t = 1; t < MT; t++) mx = fmaxf(mx, lt[t]);
        float ssum = 0.f;
        #pragma unroll
        for (int t = 0; t < MT; t++) { e[t] = __expf(lt[t] - mx); ssum += e[t]; }
        float pr = (1.0f / MM) / ssum;
        #pragma unroll
        for (int t = 0; t < MT; t++) e[t] *= pr;

        float* Trow = &sT[k][m][0];
        ((float4*)Trow)[0] = make_float4(e[0], e[1], e[2], e[3]);
        ((float4*)Trow)[1] = make_float4(e[4], e[5], e[6], e[7]);
        ((float2*)Trow)[4] = make_float2(e[8], e[9]);
        __syncthreads();   // A: T ready

        // lanes m<10: q column sum + shared W0[s] = C2[s] . T0
        if (m < MT) {
            float qv = 0.f;
            #pragma unroll
            for (int b = 0; b < MM; b++) qv += sT[k][b][m];
            sq[k][m] = qv;
            w0own = dot10p(&sC2[k][m][0], &sT[k][0][0]);
        }
        __syncthreads();   // B: q ready

        // lanes m<10: Zq = C2.q, constC2 = C2s.q (fused), publish U vectors
        if (m < MT) {
            float qr[MT];
            {
                const float4* qp = (const float4*)&sq[k][0];
                float4 a = qp[0], b4 = qp[1];
                float2 c = *(const float2*)&sq[k][8];
                qr[0]=a.x; qr[1]=a.y; qr[2]=a.z; qr[3]=a.w;
                qr[4]=b4.x; qr[5]=b4.y; qr[6]=b4.z; qr[7]=b4.w;
                qr[8]=c.x; qr[9]=c.y;
            }
            float zq = 0.f, cc = 0.f;
            const float* crow = &sC2[k][m][0];
            #pragma unroll
            for (int b = 0; b < MT; b++) {
                float c = crow[b];
                float t1 = qr[b] * c;
                zq += t1;
                cc = fmaf(t1, c, cc);
            }
            float gcs = cA * cc;
            sU [k][m] = cY * w0own - gcs;
            sU0[k][m] = cY * fmaf(sc00[k], w0own, zq) - gcs;
        }

        // meanwhile: sparse residual res[s] = sum_b C2[s] . T_b  (own bits)
        float res[MT];
        #pragma unroll
        for (int t = 0; t < MT; t++) res[t] = 0.f;
        unsigned rm = resmask;
        while (rm) {
            int b = __ffs(rm) - 1; rm &= rm - 1;
            const float* tb = &sT[k][b][0];
            float4 p0 = *(const float4*)tb;
            float4 p1 = *(const float4*)(tb + 4);
            float2 p2 = *(const float2*)(tb + 8);
            unsigned long long b0 = pack2(p0.x, p0.y);
            unsigned long long b1 = pack2(p0.z, p0.w);
            unsigned long long b2 = pack2(p1.x, p1.y);
            unsigned long long b3 = pack2(p1.z, p1.w);
            unsigned long long b4 = pack2(p2.x, p2.y);
            #pragma unroll
            for (int s = 0; s < MT; s++)
                res[s] += dot10r(&sC2[k][s][0], b0, b1, b2, b3, b4);
        }
        __syncthreads();   // C: U ready

        // update: lt[s] += U[s] - basec[s] + cY*res[s]
        const float* Ur = (m == 0) ? &sU0[k][0] : &sU[k][0];
        float4 u0 = *(const float4*)Ur;
        float4 u1 = *(const float4*)(Ur + 4);
        float2 u2 = *(const float2*)(Ur + 8);
        lt[0] += u0.x - basec[0] + cY * res[0];
        lt[1] += u0.y - basec[1] + cY * res[1];
        lt[2] += u0.z - basec[2] + cY * res[2];
        lt[3] += u0.w - basec[3] + cY * res[3];
        lt[4] += u1.x - basec[4] + cY * res[4];
        lt[5] += u1.y - basec[5] + cY * res[5];
        lt[6] += u1.z - basec[6] + cY * res[6];
        lt[7] += u1.w - basec[7] + cY * res[7];
        lt[8] += u2.x - basec[8] + cY * res[8];
        lt[9] += u2.y - basec[9] + cY * res[9];
    }

    // final marginal q from one more softmax
    {
        float mx = lt[0];
        #pragma unroll
        for (int t = 1; t < MT; t++) mx = fmaxf(mx, lt[t]);
        float ssum = 0.f;
        #pragma unroll
        for (int t = 0; t < MT; t++) { e[t] = __expf(lt[t] - mx); ssum += e[t]; }
        float pr = (1.0f / MM) / ssum;
        #pragma unroll
        for (int t = 0; t < MT; t++) e[t] *= pr;
        float* Trow = &sT[k][m][0];
        ((float4*)Trow)[0] = make_float4(e[0], e[1], e[2], e[3]);
        ((float4*)Trow)[1] = make_float4(e[4], e[5], e[6], e[7]);
        ((float2*)Trow)[4] = make_float2(e[8], e[9]);
        __syncthreads();
        if (m < MT) {
            float qv = 0.f;
            #pragma unroll
            for (int b = 0; b < MM; b++) qv += sT[k][b][m];
            out[(size_t)n * NKT + k * MT + m] = qv;
        }
    }
}

// ---------------- launch ----------------
extern "C" void kernel_launch(void* const* d_in, const int* in_sizes, int n_in,
                              void* d_out, int out_size) {
    const float* x      = (const float*)d_in[0];
    const int*   eidx   = (const int*)d_in[1];
    const float* C2g    = (const float*)d_in[2];
    const float* F2     = (const float*)d_in[3];
    const float* alpha0 = (const float*)d_in[4];
    float* out = (float*)d_out;

    const int* dst = eidx + NN * DEG;   // row 1 of edge_index

    k_setup<<<1, 256>>>(alpha0, F2);
    k_gemm<<<(NN + 63) / 64, 256>>>(x, F2);
    int tot = NN * MM;
    k_buildB<<<(tot + 127) / 128, 128>>>(dst);
    k_sym<<<(tot + 127) / 128, 128>>>();
    k_main<<<NN, 272>>>(C2g, out);
}

// round 5
// speedup vs baseline: 2.2135x; 2.2135x over previous
#include <cuda_runtime.h>
#include <cuda_bf16.h>

#define NN    6000
#define DEG   16
#define MM    17      // DEG+1
#define NT    16
#define MT    10
#define MTP   12      // padded row (floats)
#define NF    128
#define NKT   (NT*MT) // 160
#define REGc  0.1f

// ---------------- device scratch (no cudaMalloc allowed) ----------------
__device__ int      g_nbrs[NN * MM];
__device__ unsigned g_B[NN * MM];
__device__ unsigned g_mask[NN * MM];
__device__ float    g_f2n[NKT];
__device__ float    g_consts[3];     // cA = 2a/REG, cY = 4a/REG, cM = (1-a)/REG
__device__ float    g_D[NN * NKT];   // cM*(f2n[kt] - 2 * x[u] . F2[kt])

// packed f32x2 dot over 10 elements (both operands 16B-aligned smem rows)
__device__ __forceinline__ float dot10p(const float* __restrict__ a,
                                        const float* __restrict__ b) {
    const ulonglong2* A = (const ulonglong2*)a;
    const ulonglong2* B = (const ulonglong2*)b;
    ulonglong2 A0 = A[0], A1 = A[1];
    ulonglong2 B0 = B[0], B1 = B[1];
    unsigned long long a2 = *(const unsigned long long*)(a + 8);
    unsigned long long b2 = *(const unsigned long long*)(b + 8);
    unsigned long long acc;
    asm("mul.rn.f32x2 %0, %1, %2;"     : "=l"(acc) : "l"(A0.x), "l"(B0.x));
    asm("fma.rn.f32x2 %0, %1, %2, %0;" : "+l"(acc) : "l"(A0.y), "l"(B0.y));
    asm("fma.rn.f32x2 %0, %1, %2, %0;" : "+l"(acc) : "l"(A1.x), "l"(B1.x));
    asm("fma.rn.f32x2 %0, %1, %2, %0;" : "+l"(acc) : "l"(A1.y), "l"(B1.y));
    asm("fma.rn.f32x2 %0, %1, %2, %0;" : "+l"(acc) : "l"(a2),   "l"(b2));
    unsigned lo, hi;
    asm("mov.b64 {%0,%1}, %2;" : "=r"(lo), "=r"(hi) : "l"(acc));
    return __uint_as_float(lo) + __uint_as_float(hi);
}

// ---------------- setup: constants + |F2|^2 ----------------
__global__ void k_setup(const float* __restrict__ alpha0,
                        const float* __restrict__ F2) {
    int tid = threadIdx.x;
    if (tid == 0) {
        float a0 = alpha0[0];
        float alpha = 1.0f / (1.0f + __expf(-a0));
        g_consts[0] = 2.0f * alpha / REGc;
        g_consts[1] = 4.0f * alpha / REGc;
        g_consts[2] = (1.0f - alpha) / REGc;
    }
    for (int idx = tid; idx < NKT; idx += blockDim.x) {
        const float* row = F2 + (size_t)idx * NF;
        float s = 0.f;
        #pragma unroll 8
        for (int f = 0; f < NF; f++) { float v = row[f]; s += v * v; }
        g_f2n[idx] = s;
    }
}

// ---------------- GEMM: D = cM*(f2n - 2 * x @ F2^T) ----------------
__global__ void __launch_bounds__(256, 4)
k_gemm(const float* __restrict__ x, const float* __restrict__ F2) {
    __shared__ float sX[32][65];
    __shared__ float sF[32][161];

    const int tid = threadIdx.x;
    const int tr  = tid & 15;
    const int tc  = tid >> 4;
    const int r0  = blockIdx.x * 64;

    float acc[4][10];
    #pragma unroll
    for (int i = 0; i < 4; i++)
        #pragma unroll
        for (int j = 0; j < 10; j++) acc[i][j] = 0.f;

    for (int k0 = 0; k0 < NF; k0 += 32) {
        __syncthreads();
        for (int idx = tid; idx < 512; idx += 256) {
            int rr = idx >> 3, c4 = idx & 7;
            int gr = r0 + rr;
            float4 v = (gr < NN) ? __ldg((const float4*)(x + (size_t)gr * NF + k0) + c4)
                                 : make_float4(0.f, 0.f, 0.f, 0.f);
            sX[c4*4+0][rr] = v.x; sX[c4*4+1][rr] = v.y;
            sX[c4*4+2][rr] = v.z; sX[c4*4+3][rr] = v.w;
        }
        for (int idx = tid; idx < 1280; idx += 256) {
            int cc = idx >> 3, c4 = idx & 7;
            float4 v = __ldg((const float4*)(F2 + (size_t)cc * NF + k0) + c4);
            sF[c4*4+0][cc] = v.x; sF[c4*4+1][cc] = v.y;
            sF[c4*4+2][cc] = v.z; sF[c4*4+3][cc] = v.w;
        }
        __syncthreads();

        #pragma unroll 4
        for (int kk = 0; kk < 32; kk++) {
            float b[10];
            #pragma unroll
            for (int j = 0; j < 10; j++) b[j] = sF[kk][tc*10 + j];
            #pragma unroll
            for (int i = 0; i < 4; i++) {
                float a = sX[kk][tr + 16*i];
                #pragma unroll
                for (int j = 0; j < 10; j++) acc[i][j] = fmaf(a, b[j], acc[i][j]);
            }
        }
    }

    const float cM = g_consts[2];
    float f2c[10];
    #pragma unroll
    for (int j = 0; j < 10; j++) f2c[j] = g_f2n[tc*10 + j];
    #pragma unroll
    for (int i = 0; i < 4; i++) {
        int r = r0 + tr + 16*i;
        if (r < NN) {
            float* drow = g_D + (size_t)r * NKT + tc*10;
            #pragma unroll
            for (int j = 0; j < 10; j++)
                drow[j] = cM * (f2c[j] - 2.0f * acc[i][j]);
        }
    }
}

// ---------------- build directed-adjacency bitmasks B ----------------
__global__ void k_buildB(const int* __restrict__ dst) {
    int gid = blockIdx.x * blockDim.x + threadIdx.x;
    if (gid >= NN * MM) return;
    int n = gid / MM;
    int i = gid - n * MM;
    const int* dstn = dst + (size_t)n * DEG;
    int u = (i == 0) ? n : dstn[i - 1];
    g_nbrs[gid] = u;

    const int* dstu = dst + (size_t)u * DEG;
    int du[DEG];
    #pragma unroll
    for (int e = 0; e < DEG; e++) du[e] = dstu[e];
    int dn[DEG];
    #pragma unroll
    for (int e = 0; e < DEG; e++) dn[e] = dstn[e];

    unsigned bits = 0;
    #pragma unroll
    for (int j = 0; j < MM; j++) {
        int v = (j == 0) ? n : dn[j - 1];
        bool hit = false;
        #pragma unroll
        for (int e = 0; e < DEG; e++) hit |= (du[e] == v);
        bits |= (unsigned)hit << j;
    }
    g_B[gid] = bits;
}

// ---------------- symmetrize: C1 = B | B^T ----------------
__global__ void k_sym() {
    int gid = blockIdx.x * blockDim.x + threadIdx.x;
    if (gid >= NN * MM) return;
    int n = gid / MM;
    int i = gid - n * MM;
    unsigned mk = g_B[gid];
    const unsigned* Bn = g_B + n * MM;
    #pragma unroll
    for (int j = 0; j < MM; j++)
        mk |= ((Bn[j] >> i) & 1u) << j;
    g_mask[gid] = mk;
}

// ---------------- main: 10 mirror-descent iters + q ----------------
__global__ void __launch_bounds__(272, 4)
k_main(const float* __restrict__ C2g, float* __restrict__ out) {
    __shared__ __align__(16) float sT [NT][MM][MTP];
    __shared__ __align__(16) float sB [NT][MM][MTP];   // per-thread basec rows
    __shared__ __align__(16) float sC2[NT][MT][MTP];
    __shared__ __align__(16) float sq [NT][MTP];
    __shared__ __align__(16) float sU [NT][MTP];   // cY*W0 - cA*constC2   (m>=1)
    __shared__ __align__(16) float sU0[NT][MTP];   // cY*(Zq + c00w*W0) - cA*constC2 (m==0)
    __shared__ float sc00[NT];

    const int tid = threadIdx.x;
    const int n   = blockIdx.x;
    const int k   = tid / MM;
    const int m   = tid - k * MM;

    // cooperative load of C2 into padded smem
    for (int idx = tid; idx < NT * MT * MTP; idx += 272) {
        int kk = idx / (MT * MTP);
        int r  = idx - kk * MT * MTP;
        int s  = r / MTP;
        int t  = r - s * MTP;
        ((float*)sC2)[idx] = (t < MT) ? C2g[(kk * MT + s) * MT + t] : 0.f;
    }

    const float cA = g_consts[0];
    const float cY = g_consts[1];

    // per-thread t-varying cost term (t-constant parts cancel in softmax)
    // -> parked in shared memory to keep register pressure low
    const int u = g_nbrs[n * MM + m];
    {
        const float2* drow = (const float2*)(g_D + (size_t)u * NKT + k * MT);
        float2 v0 = __ldg(drow + 0);
        float2 v1 = __ldg(drow + 1);
        float2 v2 = __ldg(drow + 2);
        float2 v3 = __ldg(drow + 3);
        float2 v4 = __ldg(drow + 4);
        float* br = &sB[k][m][0];
        ((float4*)br)[0] = make_float4(v0.x, v0.y, v1.x, v1.y);
        ((float4*)br)[1] = make_float4(v2.x, v2.y, v3.x, v3.y);
        ((float2*)br)[4] = make_float2(v4.x, v4.y);
    }

    const unsigned mask = g_mask[n * MM + m];
    const unsigned resmask = (m == 0) ? 0u : (mask & ~1u);
    if (m == 0) sc00[k] = (mask & 1u) ? 0.f : -1.f;   // C1[0,0] - 1

    float lt[MT];
    #pragma unroll
    for (int t = 0; t < MT; t++) lt[t] = 0.f;
    float w0own = 0.f;

    __syncthreads();

    #pragma unroll 1
    for (int it = 0; it < 10; it++) {
        // softmax row in registers; T = p * softmax
        float mx = lt[0];
        #pragma unroll
        for (int t = 1; t < MT; t++) mx = fmaxf(mx, lt[t]);
        float e[MT];
        float ssum = 0.f;
        #pragma unroll
        for (int t = 0; t < MT; t++) { e[t] = __expf(lt[t] - mx); ssum += e[t]; }
        float pr = (1.0f / MM) / ssum;
        #pragma unroll
        for (int t = 0; t < MT; t++) e[t] *= pr;

        float* Trow = &sT[k][m][0];
        ((float4*)Trow)[0] = make_float4(e[0], e[1], e[2], e[3]);
        ((float4*)Trow)[1] = make_float4(e[4], e[5], e[6], e[7]);
        ((float2*)Trow)[4] = make_float2(e[8], e[9]);
        __syncthreads();   // A: T ready

        // lanes m<10: q column sum + shared W0[s] = C2[s] . T0
        if (m < MT) {
            float qv = 0.f;
            #pragma unroll
            for (int b = 0; b < MM; b++) qv += sT[k][b][m];
            sq[k][m] = qv;
            w0own = dot10p(&sC2[k][m][0], &sT[k][0][0]);
        }
        __syncthreads();   // B: q ready

        // lanes m<10: Zq = C2.q, constC2 = C2s.q (fused), publish U vectors
        if (m < MT) {
            float qr[MT];
            {
                const float4* qp = (const float4*)&sq[k][0];
                float4 a = qp[0], b4 = qp[1];
                float2 c = *(const float2*)&sq[k][8];
                qr[0]=a.x; qr[1]=a.y; qr[2]=a.z; qr[3]=a.w;
                qr[4]=b4.x; qr[5]=b4.y; qr[6]=b4.z; qr[7]=b4.w;
                qr[8]=c.x; qr[9]=c.y;
            }
            float zq = 0.f, cc = 0.f;
            const float* crow = &sC2[k][m][0];
            #pragma unroll
            for (int b = 0; b < MT; b++) {
                float c = crow[b];
                float t1 = qr[b] * c;
                zq += t1;
                cc = fmaf(t1, c, cc);
            }
            float gcs = cA * cc;
            sU [k][m] = cY * w0own - gcs;
            sU0[k][m] = cY * fmaf(sc00[k], w0own, zq) - gcs;
        }

        // meanwhile: sparse residual folded straight into lt (own bits)
        unsigned rm = resmask;
        while (rm) {
            int b = __ffs(rm) - 1; rm &= rm - 1;
            const float* tb = &sT[k][b][0];
            float4 p0 = *(const float4*)tb;
            float4 p1 = *(const float4*)(tb + 4);
            float2 p2 = *(const float2*)(tb + 8);
            #pragma unroll
            for (int s = 0; s < MT; s++) {
                const float* crow = &sC2[k][s][0];
                float d = crow[0]*p0.x + crow[1]*p0.y + crow[2]*p0.z + crow[3]*p0.w
                        + crow[4]*p1.x + crow[5]*p1.y + crow[6]*p1.z + crow[7]*p1.w
                        + crow[8]*p2.x + crow[9]*p2.y;
                lt[s] = fmaf(cY, d, lt[s]);
            }
        }
        __syncthreads();   // C: U ready

        // update: lt[s] += U[s] - basec[s]
        const float* Ur = (m == 0) ? &sU0[k][0] : &sU[k][0];
        const float* br = &sB[k][m][0];
        float4 u0 = *(const float4*)Ur;
        float4 u1 = *(const float4*)(Ur + 4);
        float2 u2 = *(const float2*)(Ur + 8);
        float4 b0 = *(const float4*)br;
        float4 b1 = *(const float4*)(br + 4);
        float2 b2 = *(const float2*)(br + 8);
        lt[0] += u0.x - b0.x; lt[1] += u0.y - b0.y;
        lt[2] += u0.z - b0.z; lt[3] += u0.w - b0.w;
        lt[4] += u1.x - b1.x; lt[5] += u1.y - b1.y;
        lt[6] += u1.z - b1.z; lt[7] += u1.w - b1.w;
        lt[8] += u2.x - b2.x; lt[9] += u2.y - b2.y;
    }

    // final marginal q from one more softmax
    {
        float mx = lt[0];
        #pragma unroll
        for (int t = 1; t < MT; t++) mx = fmaxf(mx, lt[t]);
        float e[MT];
        float ssum = 0.f;
        #pragma unroll
        for (int t = 0; t < MT; t++) { e[t] = __expf(lt[t] - mx); ssum += e[t]; }
        float pr = (1.0f / MM) / ssum;
        #pragma unroll
        for (int t = 0; t < MT; t++) e[t] *= pr;
        float* Trow = &sT[k][m][0];
        ((float4*)Trow)[0] = make_float4(e[0], e[1], e[2], e[3]);
        ((float4*)Trow)[1] = make_float4(e[4], e[5], e[6], e[7]);
        ((float2*)Trow)[4] = make_float2(e[8], e[9]);
        __syncthreads();
        if (m < MT) {
            float qv = 0.f;
            #pragma unroll
            for (int b = 0; b < MM; b++) qv += sT[k][b][m];
            out[(size_t)n * NKT + k * MT + m] = qv;
        }
    }
}

// ---------------- launch ----------------
extern "C" void kernel_launch(void* const* d_in, const int* in_sizes, int n_in,
                              void* d_out, int out_size) {
    const float* x      = (const float*)d_in[0];
    const int*   eidx   = (const int*)d_in[1];
    const float* C2g    = (const float*)d_in[2];
    const float* F2     = (const float*)d_in[3];
    const float* alpha0 = (const float*)d_in[4];
    float* out = (float*)d_out;

    const int* dst = eidx + NN * DEG;   // row 1 of edge_index

    k_setup<<<1, 256>>>(alpha0, F2);
    k_gemm<<<(NN + 63) / 64, 256>>>(x, F2);
    int tot = NN * MM;
    k_buildB<<<(tot + 127) / 128, 128>>>(dst);
    k_sym<<<(tot + 127) / 128, 128>>>();
    k_main<<<NN, 272>>>(C2g, out);
}

// round 6
// speedup vs baseline: 2.5647x; 1.1586x over previous
#include <cuda_runtime.h>
#include <cuda_bf16.h>

#define NN    6000
#define DEG   16
#define MM    17      // DEG+1
#define NT    16
#define MT    10
#define MTP   12      // padded row (floats)
#define NF    128
#define NKT   (NT*MT) // 160
#define REGc  0.1f

// ---------------- device scratch (no cudaMalloc allowed) ----------------
__device__ int      g_nbrs[NN * MM];
__device__ unsigned g_mask[NN * MM];
__device__ float    g_f2n[NKT];
__device__ float    g_consts[3];     // cA = 2a/REG, cY = 4a/REG, cM = (1-a)/REG
__device__ float    g_D[NN * NKT];   // cM*(f2n[kt] - 2 * x[u] . F2[kt])

// ---------------- setup: constants + |F2|^2 ----------------
__global__ void k_setup(const float* __restrict__ alpha0,
                        const float* __restrict__ F2) {
    int tid = threadIdx.x;
    if (tid == 0) {
        float a0 = alpha0[0];
        float alpha = 1.0f / (1.0f + __expf(-a0));
        g_consts[0] = 2.0f * alpha / REGc;
        g_consts[1] = 4.0f * alpha / REGc;
        g_consts[2] = (1.0f - alpha) / REGc;
    }
    for (int idx = tid; idx < NKT; idx += blockDim.x) {
        const float* row = F2 + (size_t)idx * NF;
        float s = 0.f;
        #pragma unroll 8
        for (int f = 0; f < NF; f++) { float v = row[f]; s += v * v; }
        g_f2n[idx] = s;
    }
}

// ---------------- GEMM: D = cM*(f2n - 2 * x @ F2^T) ----------------
__global__ void __launch_bounds__(256, 4)
k_gemm(const float* __restrict__ x, const float* __restrict__ F2) {
    __shared__ float sX[32][65];
    __shared__ float sF[32][161];

    const int tid = threadIdx.x;
    const int tr  = tid & 15;
    const int tc  = tid >> 4;
    const int r0  = blockIdx.x * 64;

    float acc[4][10];
    #pragma unroll
    for (int i = 0; i < 4; i++)
        #pragma unroll
        for (int j = 0; j < 10; j++) acc[i][j] = 0.f;

    for (int k0 = 0; k0 < NF; k0 += 32) {
        __syncthreads();
        for (int idx = tid; idx < 512; idx += 256) {
            int rr = idx >> 3, c4 = idx & 7;
            int gr = r0 + rr;
            float4 v = (gr < NN) ? __ldg((const float4*)(x + (size_t)gr * NF + k0) + c4)
                                 : make_float4(0.f, 0.f, 0.f, 0.f);
            sX[c4*4+0][rr] = v.x; sX[c4*4+1][rr] = v.y;
            sX[c4*4+2][rr] = v.z; sX[c4*4+3][rr] = v.w;
        }
        for (int idx = tid; idx < 1280; idx += 256) {
            int cc = idx >> 3, c4 = idx & 7;
            float4 v = __ldg((const float4*)(F2 + (size_t)cc * NF + k0) + c4);
            sF[c4*4+0][cc] = v.x; sF[c4*4+1][cc] = v.y;
            sF[c4*4+2][cc] = v.z; sF[c4*4+3][cc] = v.w;
        }
        __syncthreads();

        #pragma unroll 4
        for (int kk = 0; kk < 32; kk++) {
            float b[10];
            #pragma unroll
            for (int j = 0; j < 10; j++) b[j] = sF[kk][tc*10 + j];
            #pragma unroll
            for (int i = 0; i < 4; i++) {
                float a = sX[kk][tr + 16*i];
                #pragma unroll
                for (int j = 0; j < 10; j++) acc[i][j] = fmaf(a, b[j], acc[i][j]);
            }
        }
    }

    const float cM = g_consts[2];
    float f2c[10];
    #pragma unroll
    for (int j = 0; j < 10; j++) f2c[j] = g_f2n[tc*10 + j];
    #pragma unroll
    for (int i = 0; i < 4; i++) {
        int r = r0 + tr + 16*i;
        if (r < NN) {
            float* drow = g_D + (size_t)r * NKT + tc*10;
            #pragma unroll
            for (int j = 0; j < 10; j++)
                drow[j] = cM * (f2c[j] - 2.0f * acc[i][j]);
        }
    }
}

// ---------------- fused adjacency: build B then symmetrize, 16 nodes/block ----
#define NPB 16
__global__ void __launch_bounds__(NPB * MM, 4)
k_adj(const int* __restrict__ dst) {
    __shared__ unsigned sB[NPB][MM];

    const int tid = threadIdx.x;           // 0..271
    const int ln  = tid / MM;              // local node 0..15
    const int i   = tid - ln * MM;         // row 0..16
    const int n   = blockIdx.x * NPB + ln;
    const bool ok = (n < NN);

    if (ok) {
        const int* dstn = dst + (size_t)n * DEG;
        int u = (i == 0) ? n : dstn[i - 1];
        g_nbrs[n * MM + i] = u;

        const int* dstu = dst + (size_t)u * DEG;
        int du[DEG];
        #pragma unroll
        for (int e = 0; e < DEG; e++) du[e] = dstu[e];
        int dn[DEG];
        #pragma unroll
        for (int e = 0; e < DEG; e++) dn[e] = dstn[e];

        unsigned bits = 0;
        #pragma unroll
        for (int j = 0; j < MM; j++) {
            int v = (j == 0) ? n : dn[j - 1];
            bool hit = false;
            #pragma unroll
            for (int e = 0; e < DEG; e++) hit |= (du[e] == v);
            bits |= (unsigned)hit << j;
        }
        sB[ln][i] = bits;
    }
    __syncthreads();
    if (ok) {
        unsigned mk = sB[ln][i];
        #pragma unroll
        for (int j = 0; j < MM; j++)
            mk |= ((sB[ln][j] >> i) & 1u) << j;
        g_mask[n * MM + i] = mk;
    }
}

// ---------------- main: 10 mirror-descent iters + q, 2 barriers/iter ----------
__global__ void __launch_bounds__(272, 3)
k_main(const float* __restrict__ C2g, float* __restrict__ out) {
    __shared__ __align__(16) float sT [NT][MM][MTP];
    __shared__ __align__(16) float sC2[NT][MT][MTP];
    __shared__ __align__(16) float sU [NT][MTP];   // cY*W0 - cA*constC2   (m>=1)
    __shared__ __align__(16) float sU0[NT][MTP];   // cY*(Zq + c00w*W0) - cA*constC2 (m==0)
    __shared__ float sc00[NT];

    const int tid = threadIdx.x;
    const int n   = blockIdx.x;
    const int k   = tid / MM;
    const int m   = tid - k * MM;

    // cooperative load of C2 into padded smem
    for (int idx = tid; idx < NT * MT * MTP; idx += 272) {
        int kk = idx / (MT * MTP);
        int r  = idx - kk * MT * MTP;
        int s  = r / MTP;
        int t  = r - s * MTP;
        ((float*)sC2)[idx] = (t < MT) ? C2g[(kk * MT + s) * MT + t] : 0.f;
    }

    const float cA = g_consts[0];
    const float cY = g_consts[1];

    // per-thread t-varying cost term (t-constant parts cancel in softmax)
    const int u = g_nbrs[n * MM + m];
    float basec[MT];
    {
        const float2* drow = (const float2*)(g_D + (size_t)u * NKT + k * MT);
        #pragma unroll
        for (int h = 0; h < 5; h++) {
            float2 v = __ldg(drow + h);
            basec[2*h]   = v.x;
            basec[2*h+1] = v.y;
        }
    }

    const unsigned mask = g_mask[n * MM + m];
    const unsigned resmask = (m == 0) ? 0u : (mask & ~1u);
    if (m == 0) sc00[k] = (mask & 1u) ? 0.f : -1.f;   // C1[0,0] - 1

    float lt[MT];
    #pragma unroll
    for (int t = 0; t < MT; t++) lt[t] = 0.f;
    float e[MT];

    __syncthreads();

    #pragma unroll 1
    for (int it = 0; it < 10; it++) {
        // softmax row in registers; T = p * softmax
        float mx = lt[0];
        #pragma unroll
        for (int t = 1; t < MT; t++) mx = fmaxf(mx, lt[t]);
        float ssum = 0.f;
        #pragma unroll
        for (int t = 0; t < MT; t++) { e[t] = __expf(lt[t] - mx); ssum += e[t]; }
        float pr = (1.0f / MM) / ssum;
        #pragma unroll
        for (int t = 0; t < MT; t++) e[t] *= pr;

        float* Trow = &sT[k][m][0];
        ((float4*)Trow)[0] = make_float4(e[0], e[1], e[2], e[3]);
        ((float4*)Trow)[1] = make_float4(e[4], e[5], e[6], e[7]);
        ((float2*)Trow)[4] = make_float2(e[8], e[9]);
        __syncthreads();   // A: T ready

        // lanes m<10: full q vector + own U row, all local
        if (m < MT) {
            // q = column sums over 17 rows (vectorized row reads)
            float4 qa = make_float4(0.f, 0.f, 0.f, 0.f);
            float4 qb = make_float4(0.f, 0.f, 0.f, 0.f);
            float2 qc = make_float2(0.f, 0.f);
            #pragma unroll
            for (int b = 0; b < MM; b++) {
                const float* tb = &sT[k][b][0];
                float4 p0 = *(const float4*)tb;
                float4 p1 = *(const float4*)(tb + 4);
                float2 p2 = *(const float2*)(tb + 8);
                qa.x += p0.x; qa.y += p0.y; qa.z += p0.z; qa.w += p0.w;
                qb.x += p1.x; qb.y += p1.y; qb.z += p1.z; qb.w += p1.w;
                qc.x += p2.x; qc.y += p2.y;
            }
            float q[MT] = {qa.x, qa.y, qa.z, qa.w, qb.x, qb.y, qb.z, qb.w, qc.x, qc.y};

            // own C2 row
            const float* crp = &sC2[k][m][0];
            float4 c0 = *(const float4*)crp;
            float4 c1 = *(const float4*)(crp + 4);
            float2 c2 = *(const float2*)(crp + 8);
            float cr[MT] = {c0.x, c0.y, c0.z, c0.w, c1.x, c1.y, c1.z, c1.w, c2.x, c2.y};

            // T0 row
            const float* t0p = &sT[k][0][0];
            float4 a0 = *(const float4*)t0p;
            float4 a1 = *(const float4*)(t0p + 4);
            float2 a2 = *(const float2*)(t0p + 8);
            float t0[MT] = {a0.x, a0.y, a0.z, a0.w, a1.x, a1.y, a1.z, a1.w, a2.x, a2.y};

            float w0 = 0.f, zq = 0.f, cc = 0.f;
            #pragma unroll
            for (int t = 0; t < MT; t++) {
                float c = cr[t];
                w0 = fmaf(c, t0[t], w0);
                float t1 = c * q[t];
                zq += t1;
                cc = fmaf(t1, c, cc);
            }
            float gcs = cA * cc;
            sU [k][m] = cY * w0 - gcs;
            sU0[k][m] = cY * fmaf(sc00[k], w0, zq) - gcs;
        }

        // sparse residual folded straight into lt (own bits; m==0 has none)
        unsigned rm = resmask;
        while (rm) {
            int b = __ffs(rm) - 1; rm &= rm - 1;
            const float* tb = &sT[k][b][0];
            float4 p0 = *(const float4*)tb;
            float4 p1 = *(const float4*)(tb + 4);
            float2 p2 = *(const float2*)(tb + 8);
            #pragma unroll
            for (int s = 0; s < MT; s++) {
                const float* crp = &sC2[k][s][0];
                float4 c0 = *(const float4*)crp;
                float4 c1 = *(const float4*)(crp + 4);
                float2 c2 = *(const float2*)(crp + 8);
                float d = c0.x*p0.x + c0.y*p0.y + c0.z*p0.z + c0.w*p0.w
                        + c1.x*p1.x + c1.y*p1.y + c1.z*p1.z + c1.w*p1.w
                        + c2.x*p2.x + c2.y*p2.y;
                lt[s] = fmaf(cY, d, lt[s]);
            }
        }
        __syncthreads();   // C: U ready

        // update: lt[s] += U[s] - basec[s]
        const float* Ur = (m == 0) ? &sU0[k][0] : &sU[k][0];
        float4 u0 = *(const float4*)Ur;
        float4 u1 = *(const float4*)(Ur + 4);
        float2 u2 = *(const float2*)(Ur + 8);
        lt[0] += u0.x - basec[0]; lt[1] += u0.y - basec[1];
        lt[2] += u0.z - basec[2]; lt[3] += u0.w - basec[3];
        lt[4] += u1.x - basec[4]; lt[5] += u1.y - basec[5];
        lt[6] += u1.z - basec[6]; lt[7] += u1.w - basec[7];
        lt[8] += u2.x - basec[8]; lt[9] += u2.y - basec[9];
    }

    // final marginal q from one more softmax
    {
        float mx = lt[0];
        #pragma unroll
        for (int t = 1; t < MT; t++) mx = fmaxf(mx, lt[t]);
        float ssum = 0.f;
        #pragma unroll
        for (int t = 0; t < MT; t++) { e[t] = __expf(lt[t] - mx); ssum += e[t]; }
        float pr = (1.0f / MM) / ssum;
        #pragma unroll
        for (int t = 0; t < MT; t++) e[t] *= pr;
        float* Trow = &sT[k][m][0];
        ((float4*)Trow)[0] = make_float4(e[0], e[1], e[2], e[3]);
        ((float4*)Trow)[1] = make_float4(e[4], e[5], e[6], e[7]);
        ((float2*)Trow)[4] = make_float2(e[8], e[9]);
        __syncthreads();
        if (m < MT) {
            float qv = 0.f;
            #pragma unroll
            for (int b = 0; b < MM; b++) qv += sT[k][b][m];
            out[(size_t)n * NKT + k * MT + m] = qv;
        }
    }
}

// ---------------- launch ----------------
extern "C" void kernel_launch(void* const* d_in, const int* in_sizes, int n_in,
                              void* d_out, int out_size) {
    const float* x      = (const float*)d_in[0];
    const int*   eidx   = (const int*)d_in[1];
    const float* C2g    = (const float*)d_in[2];
    const float* F2     = (const float*)d_in[3];
    const float* alpha0 = (const float*)d_in[4];
    float* out = (float*)d_out;

    const int* dst = eidx + NN * DEG;   // row 1 of edge_index

    k_setup<<<1, 256>>>(alpha0, F2);
    k_gemm<<<(NN + 63) / 64, 256>>>(x, F2);
    k_adj<<<(NN + NPB - 1) / NPB, NPB * MM>>>(dst);
    k_main<<<NN, 272>>>(C2g, out);
}

// round 7
// speedup vs baseline: 6.8822x; 2.6834x over previous
#include <cuda_runtime.h>
#include <cuda_bf16.h>

#define NN    6000
#define DEG   16
#define MM    17      // DEG+1
#define NT    16
#define MT    10
#define MTP   12      // padded row (floats)
#define NF    128
#define NKT   (NT*MT) // 160
#define REGc  0.1f

#define GEMM_BLOCKS   ((NN + 63) / 64)          // 94
#define SETUP_BLOCK   GEMM_BLOCKS               // 94
#define ADJ_BLOCK0    (GEMM_BLOCKS + 1)         // 95
#define NPB           16
#define ADJ_BLOCKS    ((NN + NPB - 1) / NPB)    // 375
#define PREP_BLOCKS   (ADJ_BLOCK0 + ADJ_BLOCKS) // 470

// ---------------- device scratch (no cudaMalloc allowed) ----------------
__device__ int      g_nbrs[NN * MM];
__device__ unsigned g_mask[NN * MM];
__device__ float    g_f2n[NKT];
__device__ float    g_consts[3];     // cA = 2a/REG, cY = 4a/REG, cM = (1-a)/REG
__device__ float    g_D[NN * NKT];   // raw dot:  x[u] . F2[kt]

// packed f32x2 dot over 10 elements (both operands 16B-aligned smem rows)
__device__ __forceinline__ float dot10p(const float* __restrict__ a,
                                        const float* __restrict__ b) {
    const ulonglong2* A = (const ulonglong2*)a;
    const ulonglong2* B = (const ulonglong2*)b;
    ulonglong2 A0 = A[0], A1 = A[1];
    ulonglong2 B0 = B[0], B1 = B[1];
    unsigned long long a2 = *(const unsigned long long*)(a + 8);
    unsigned long long b2 = *(const unsigned long long*)(b + 8);
    unsigned long long acc;
    asm("mul.rn.f32x2 %0, %1, %2;"     : "=l"(acc) : "l"(A0.x), "l"(B0.x));
    asm("fma.rn.f32x2 %0, %1, %2, %0;" : "+l"(acc) : "l"(A0.y), "l"(B0.y));
    asm("fma.rn.f32x2 %0, %1, %2, %0;" : "+l"(acc) : "l"(A1.x), "l"(B1.x));
    asm("fma.rn.f32x2 %0, %1, %2, %0;" : "+l"(acc) : "l"(A1.y), "l"(B1.y));
    asm("fma.rn.f32x2 %0, %1, %2, %0;" : "+l"(acc) : "l"(a2),   "l"(b2));
    unsigned lo, hi;
    asm("mov.b64 {%0,%1}, %2;" : "=r"(lo), "=r"(hi) : "l"(acc));
    return __uint_as_float(lo) + __uint_as_float(hi);
}

// ---------------- fused prologue: setup | gemm | adjacency ----------------
// block < 94           : GEMM tile (raw dot, no scaling)
// block == 94          : consts + |F2|^2
// block in [95, 470)   : adjacency masks, 16 nodes per block
__global__ void __launch_bounds__(272, 3)
k_prep(const float* __restrict__ x, const float* __restrict__ F2,
       const float* __restrict__ alpha0, const int* __restrict__ dst) {
    __shared__ float sX[32][65];
    __shared__ float sF[32][161];
    __shared__ unsigned sB[NPB][MM];

    const int tid = threadIdx.x;
    const int blk = blockIdx.x;

    if (blk < GEMM_BLOCKS) {
        // ---- GEMM: g_D[r][c] = x[r] . F2[c]  (6000x128 @ 128x160) ----
        const int tr = tid & 15;
        const int tc = (tid >> 4) & 15;
        const bool act = (tid < 256);
        const int r0 = blk * 64;

        float acc[4][10];
        #pragma unroll
        for (int i = 0; i < 4; i++)
            #pragma unroll
            for (int j = 0; j < 10; j++) acc[i][j] = 0.f;

        for (int k0 = 0; k0 < NF; k0 += 32) {
            __syncthreads();
            for (int idx = tid; idx < 512; idx += 272) {
                int rr = idx >> 3, c4 = idx & 7;
                int gr = r0 + rr;
                float4 v = (gr < NN) ? __ldg((const float4*)(x + (size_t)gr * NF + k0) + c4)
                                     : make_float4(0.f, 0.f, 0.f, 0.f);
                sX[c4*4+0][rr] = v.x; sX[c4*4+1][rr] = v.y;
                sX[c4*4+2][rr] = v.z; sX[c4*4+3][rr] = v.w;
            }
            for (int idx = tid; idx < 1280; idx += 272) {
                int cc = idx >> 3, c4 = idx & 7;
                float4 v = __ldg((const float4*)(F2 + (size_t)cc * NF + k0) + c4);
                sF[c4*4+0][cc] = v.x; sF[c4*4+1][cc] = v.y;
                sF[c4*4+2][cc] = v.z; sF[c4*4+3][cc] = v.w;
            }
            __syncthreads();

            if (act) {
                #pragma unroll 4
                for (int kk = 0; kk < 32; kk++) {
                    float b[10];
                    #pragma unroll
                    for (int j = 0; j < 10; j++) b[j] = sF[kk][tc*10 + j];
                    #pragma unroll
                    for (int i = 0; i < 4; i++) {
                        float a = sX[kk][tr + 16*i];
                        #pragma unroll
                        for (int j = 0; j < 10; j++) acc[i][j] = fmaf(a, b[j], acc[i][j]);
                    }
                }
            }
        }

        if (act) {
            #pragma unroll
            for (int i = 0; i < 4; i++) {
                int r = r0 + tr + 16*i;
                if (r < NN) {
                    float* drow = g_D + (size_t)r * NKT + tc*10;
                    #pragma unroll
                    for (int j = 0; j < 10; j++) drow[j] = acc[i][j];
                }
            }
        }
    } else if (blk == SETUP_BLOCK) {
        // ---- consts + |F2|^2 ----
        if (tid == 0) {
            float a0 = alpha0[0];
            float alpha = 1.0f / (1.0f + __expf(-a0));
            g_consts[0] = 2.0f * alpha / REGc;
            g_consts[1] = 4.0f * alpha / REGc;
            g_consts[2] = (1.0f - alpha) / REGc;
        }
        for (int idx = tid; idx < NKT; idx += 272) {
            const float* row = F2 + (size_t)idx * NF;
            float s = 0.f;
            #pragma unroll 8
            for (int f = 0; f < NF; f++) { float v = row[f]; s += v * v; }
            g_f2n[idx] = s;
        }
    } else {
        // ---- adjacency: build B then symmetrize, 16 nodes per block ----
        const int ln = tid / MM;
        const int i  = tid - ln * MM;
        const int n  = (blk - ADJ_BLOCK0) * NPB + ln;
        const bool ok = (n < NN) && (ln < NPB);

        if (ok) {
            const int* dstn = dst + (size_t)n * DEG;
            int u = (i == 0) ? n : dstn[i - 1];
            g_nbrs[n * MM + i] = u;

            const int* dstu = dst + (size_t)u * DEG;
            int du[DEG];
            #pragma unroll
            for (int e = 0; e < DEG; e++) du[e] = dstu[e];
            int dn[DEG];
            #pragma unroll
            for (int e = 0; e < DEG; e++) dn[e] = dstn[e];

            unsigned bits = 0;
            #pragma unroll
            for (int j = 0; j < MM; j++) {
                int v = (j == 0) ? n : dn[j - 1];
                bool hit = false;
                #pragma unroll
                for (int e = 0; e < DEG; e++) hit |= (du[e] == v);
                bits |= (unsigned)hit << j;
            }
            sB[ln][i] = bits;
        }
        __syncthreads();
        if (ok) {
            unsigned mk = sB[ln][i];
            #pragma unroll
            for (int j = 0; j < MM; j++)
                mk |= ((sB[ln][j] >> i) & 1u) << j;
            g_mask[n * MM + i] = mk;
        }
    }
}

// ---------------- main: 10 mirror-descent iters + q  (R3 structure) --------
__global__ void __launch_bounds__(272, 3)
k_main(const float* __restrict__ C2g, float* __restrict__ out) {
    __shared__ __align__(16) float sT [NT][MM][MTP];
    __shared__ __align__(16) float sW [NT][MM][MTP];   // cY * C2 . T_b for listed pairs
    __shared__ __align__(16) float sC2 [NT][MT][MTP];
    __shared__ __align__(16) float sC2s[NT][MT][MTP];
    __shared__ __align__(16) float sq [NT][MTP];
    __shared__ __align__(16) float sU [NT][MTP];       // cY*W0 - cA*constC2   (m>=1)
    __shared__ __align__(16) float sU0[NT][MTP];       // cY*(Zq + c00w*W0) - cA*constC2 (m==0)
    __shared__ float sc00[NT];
    __shared__ int   sColMask[NT];
    __shared__ int   sList[NT * MM];
    __shared__ int   sLn;

    const int tid = threadIdx.x;
    const int n   = blockIdx.x;
    const int k   = tid / MM;
    const int m   = tid - k * MM;

    // cooperative load of C2 / C2^2 into padded smem
    for (int idx = tid; idx < NT * MT * MTP; idx += 272) {
        int kk = idx / (MT * MTP);
        int r  = idx - kk * MT * MTP;
        int s  = r / MTP;
        int t  = r - s * MTP;
        float v = (t < MT) ? C2g[(kk * MT + s) * MT + t] : 0.f;
        ((float*)sC2)[idx]  = v;
        ((float*)sC2s)[idx] = v * v;
    }
    if (tid < NT) sColMask[tid] = 0;

    const float cA = g_consts[0];
    const float cY = g_consts[1];
    const float cM = g_consts[2];

    // per-thread t-varying cost term: basec[t] = cM*(f2n[kt] - 2*dot)
    const int u = g_nbrs[n * MM + m];
    float basec[MT];
    {
        const float2* drow = (const float2*)(g_D + (size_t)u * NKT + k * MT);
        const float2* frow = (const float2*)(g_f2n + k * MT);
        #pragma unroll
        for (int h = 0; h < 5; h++) {
            float2 v = __ldg(drow + h);
            float2 f = frow[h];
            basec[2*h]   = cM * (f.x - 2.0f * v.x);
            basec[2*h+1] = cM * (f.y - 2.0f * v.y);
        }
    }

    const unsigned mask = g_mask[n * MM + m];
    const unsigned resmask = (m == 0) ? 0u : (mask & ~1u);
    if (m == 0) sc00[k] = (mask & 1u) ? 0.f : -1.f;   // C1[0,0] - 1

    __syncthreads();
    if (resmask) atomicOr(&sColMask[k], (int)resmask);
    __syncthreads();
    if (tid == 0) {
        int L = 0;
        for (int kk = 0; kk < NT; kk++) {
            unsigned cm = (unsigned)sColMask[kk];
            while (cm) { int b = __ffs(cm) - 1; cm &= cm - 1; sList[L++] = (kk << 5) | b; }
        }
        sLn = L;
    }
    __syncthreads();
    const int L10 = 10 * sLn;

    float lt[MT];
    #pragma unroll
    for (int t = 0; t < MT; t++) lt[t] = 0.f;
    float e[MT];
    float w0own = 0.f;

    #pragma unroll 1
    for (int it = 0; it < 10; it++) {
        // softmax row in registers; T = p * softmax
        float mx = lt[0];
        #pragma unroll
        for (int t = 1; t < MT; t++) mx = fmaxf(mx, lt[t]);
        float ssum = 0.f;
        #pragma unroll
        for (int t = 0; t < MT; t++) { e[t] = __expf(lt[t] - mx); ssum += e[t]; }
        float pr = (1.0f / MM) / ssum;
        #pragma unroll
        for (int t = 0; t < MT; t++) e[t] *= pr;

        float* Trow = &sT[k][m][0];
        ((float4*)Trow)[0] = make_float4(e[0], e[1], e[2], e[3]);
        ((float4*)Trow)[1] = make_float4(e[4], e[5], e[6], e[7]);
        ((float2*)Trow)[4] = make_float2(e[8], e[9]);
        __syncthreads();   // A

        // lanes m<10: q column sum + shared W0[s] = C2[s] . T0
        if (m < MT) {
            float qv = 0.f;
            #pragma unroll
            for (int b = 0; b < MM; b++) qv += sT[k][b][m];
            sq[k][m] = qv;
            w0own = dot10p(&sC2[k][m][0], &sT[k][0][0]);
        }
        // worklist: residual W_b = cY * C2 . T_b, 10-lane parallel per pair
        for (int idx = tid; idx < L10; idx += 272) {
            int p = idx / 10;
            int s = idx - p * 10;
            int ent = sList[p];
            int kk = ent >> 5, b = ent & 31;
            sW[kk][b][s] = cY * dot10p(&sC2[kk][s][0], &sT[kk][b][0]);
        }
        __syncthreads();   // B

        // lanes m<10: Zq = C2 . q ; constC2 = C2s . q ; publish combined vectors
        if (m < MT) {
            float zq  = dot10p(&sC2 [k][m][0], &sq[k][0]);
            float cc  = dot10p(&sC2s[k][m][0], &sq[k][0]);
            float gcs = cA * cc;
            sU [k][m] = cY * w0own - gcs;
            sU0[k][m] = cY * fmaf(sc00[k], w0own, zq) - gcs;
        }
        __syncthreads();   // C

        // update: lt[s] += U[s] - basec[s] (+ rare residual rows)
        const float* Ur = (m == 0) ? &sU0[k][0] : &sU[k][0];
        float4 u0 = *(const float4*)Ur;
        float4 u1 = *(const float4*)(Ur + 4);
        float2 u2 = *(const float2*)(Ur + 8);
        lt[0] += u0.x - basec[0]; lt[1] += u0.y - basec[1];
        lt[2] += u0.z - basec[2]; lt[3] += u0.w - basec[3];
        lt[4] += u1.x - basec[4]; lt[5] += u1.y - basec[5];
        lt[6] += u1.z - basec[6]; lt[7] += u1.w - basec[7];
        lt[8] += u2.x - basec[8]; lt[9] += u2.y - basec[9];

        unsigned rm = resmask;
        while (rm) {
            int b = __ffs(rm) - 1; rm &= rm - 1;
            const float* Wr = &sW[k][b][0];
            float4 w0v = *(const float4*)Wr;
            float4 w1v = *(const float4*)(Wr + 4);
            float2 w2v = *(const float2*)(Wr + 8);
            lt[0] += w0v.x; lt[1] += w0v.y; lt[2] += w0v.z; lt[3] += w0v.w;
            lt[4] += w1v.x; lt[5] += w1v.y; lt[6] += w1v.z; lt[7] += w1v.w;
            lt[8] += w2v.x; lt[9] += w2v.y;
        }
    }

    // final marginal q from one more softmax
    {
        float mx = lt[0];
        #pragma unroll
        for (int t = 1; t < MT; t++) mx = fmaxf(mx, lt[t]);
        float ssum = 0.f;
        #pragma unroll
        for (int t = 0; t < MT; t++) { e[t] = __expf(lt[t] - mx); ssum += e[t]; }
        float pr = (1.0f / MM) / ssum;
        #pragma unroll
        for (int t = 0; t < MT; t++) e[t] *= pr;
        float* Trow = &sT[k][m][0];
        ((float4*)Trow)[0] = make_float4(e[0], e[1], e[2], e[3]);
        ((float4*)Trow)[1] = make_float4(e[4], e[5], e[6], e[7]);
        ((float2*)Trow)[4] = make_float2(e[8], e[9]);
        __syncthreads();
        if (m < MT) {
            float qv = 0.f;
            #pragma unroll
            for (int b = 0; b < MM; b++) qv += sT[k][b][m];
            out[(size_t)n * NKT + k * MT + m] = qv;
        }
    }
}

// ---------------- launch ----------------
extern "C" void kernel_launch(void* const* d_in, const int* in_sizes, int n_in,
                              void* d_out, int out_size) {
    const float* x      = (const float*)d_in[0];
    const int*   eidx   = (const int*)d_in[1];
    const float* C2g    = (const float*)d_in[2];
    const float* F2     = (const float*)d_in[3];
    const float* alpha0 = (const float*)d_in[4];
    float* out = (float*)d_out;

    const int* dst = eidx + NN * DEG;   // row 1 of edge_index

    k_prep<<<PREP_BLOCKS, 272>>>(x, F2, alpha0, dst);
    k_main<<<NN, 272>>>(C2g, out);
}

// round 8
// speedup vs baseline: 7.5645x; 1.0991x over previous
#include <cuda_runtime.h>
#include <cuda_bf16.h>

#define NN    6000
#define DEG   16
#define MM    17      // DEG+1
#define NT    16
#define MT    10
#define MTP   12      // padded row (floats)
#define NF    128
#define NKT   (NT*MT) // 160
#define REGc  0.1f

#define GEMM_BLOCKS   ((NN + 63) / 64)          // 94
#define SETUP_BLOCK   GEMM_BLOCKS               // 94
#define ADJ_BLOCK0    (GEMM_BLOCKS + 1)         // 95
#define NPB           16
#define ADJ_BLOCKS    ((NN + NPB - 1) / NPB)    // 375
#define PREP_BLOCKS   (ADJ_BLOCK0 + ADJ_BLOCKS) // 470

// ---------------- device scratch (no cudaMalloc allowed) ----------------
__device__ int      g_nbrs[NN * MM];
__device__ unsigned g_mask[NN * MM];
__device__ float    g_f2n[NKT];
__device__ float    g_consts[3];     // cA = 2a/REG, cY = 4a/REG, cM = (1-a)/REG
__device__ float    g_D[NN * NKT];   // raw dot:  x[u] . F2[kt]

// packed f32x2 dot over 10 elements (both operands 16B-aligned smem rows)
__device__ __forceinline__ float dot10p(const float* __restrict__ a,
                                        const float* __restrict__ b) {
    const ulonglong2* A = (const ulonglong2*)a;
    const ulonglong2* B = (const ulonglong2*)b;
    ulonglong2 A0 = A[0], A1 = A[1];
    ulonglong2 B0 = B[0], B1 = B[1];
    unsigned long long a2 = *(const unsigned long long*)(a + 8);
    unsigned long long b2 = *(const unsigned long long*)(b + 8);
    unsigned long long acc;
    asm("mul.rn.f32x2 %0, %1, %2;"     : "=l"(acc) : "l"(A0.x), "l"(B0.x));
    asm("fma.rn.f32x2 %0, %1, %2, %0;" : "+l"(acc) : "l"(A0.y), "l"(B0.y));
    asm("fma.rn.f32x2 %0, %1, %2, %0;" : "+l"(acc) : "l"(A1.x), "l"(B1.x));
    asm("fma.rn.f32x2 %0, %1, %2, %0;" : "+l"(acc) : "l"(A1.y), "l"(B1.y));
    asm("fma.rn.f32x2 %0, %1, %2, %0;" : "+l"(acc) : "l"(a2),   "l"(b2));
    unsigned lo, hi;
    asm("mov.b64 {%0,%1}, %2;" : "=r"(lo), "=r"(hi) : "l"(acc));
    return __uint_as_float(lo) + __uint_as_float(hi);
}

// ---------------- fused prologue: setup | gemm | adjacency ----------------
__global__ void __launch_bounds__(272, 3)
k_prep(const float* __restrict__ x, const float* __restrict__ F2,
       const float* __restrict__ alpha0, const int* __restrict__ dst) {
    __shared__ float sX[32][65];
    __shared__ float sF[32][161];
    __shared__ unsigned sB[NPB][MM];

    const int tid = threadIdx.x;
    const int blk = blockIdx.x;

    if (blk < GEMM_BLOCKS) {
        const int tr = tid & 15;
        const int tc = (tid >> 4) & 15;
        const bool act = (tid < 256);
        const int r0 = blk * 64;

        float acc[4][10];
        #pragma unroll
        for (int i = 0; i < 4; i++)
            #pragma unroll
            for (int j = 0; j < 10; j++) acc[i][j] = 0.f;

        for (int k0 = 0; k0 < NF; k0 += 32) {
            __syncthreads();
            for (int idx = tid; idx < 512; idx += 272) {
                int rr = idx >> 3, c4 = idx & 7;
                int gr = r0 + rr;
                float4 v = (gr < NN) ? __ldg((const float4*)(x + (size_t)gr * NF + k0) + c4)
                                     : make_float4(0.f, 0.f, 0.f, 0.f);
                sX[c4*4+0][rr] = v.x; sX[c4*4+1][rr] = v.y;
                sX[c4*4+2][rr] = v.z; sX[c4*4+3][rr] = v.w;
            }
            for (int idx = tid; idx < 1280; idx += 272) {
                int cc = idx >> 3, c4 = idx & 7;
                float4 v = __ldg((const float4*)(F2 + (size_t)cc * NF + k0) + c4);
                sF[c4*4+0][cc] = v.x; sF[c4*4+1][cc] = v.y;
                sF[c4*4+2][cc] = v.z; sF[c4*4+3][cc] = v.w;
            }
            __syncthreads();

            if (act) {
                #pragma unroll 4
                for (int kk = 0; kk < 32; kk++) {
                    float b[10];
                    #pragma unroll
                    for (int j = 0; j < 10; j++) b[j] = sF[kk][tc*10 + j];
                    #pragma unroll
                    for (int i = 0; i < 4; i++) {
                        float a = sX[kk][tr + 16*i];
                        #pragma unroll
                        for (int j = 0; j < 10; j++) acc[i][j] = fmaf(a, b[j], acc[i][j]);
                    }
                }
            }
        }

        if (act) {
            #pragma unroll
            for (int i = 0; i < 4; i++) {
                int r = r0 + tr + 16*i;
                if (r < NN) {
                    float* drow = g_D + (size_t)r * NKT + tc*10;
                    #pragma unroll
                    for (int j = 0; j < 10; j++) drow[j] = acc[i][j];
                }
            }
        }
    } else if (blk == SETUP_BLOCK) {
        if (tid == 0) {
            float a0 = alpha0[0];
            float alpha = 1.0f / (1.0f + __expf(-a0));
            g_consts[0] = 2.0f * alpha / REGc;
            g_consts[1] = 4.0f * alpha / REGc;
            g_consts[2] = (1.0f - alpha) / REGc;
        }
        for (int idx = tid; idx < NKT; idx += 272) {
            const float* row = F2 + (size_t)idx * NF;
            float s = 0.f;
            #pragma unroll 8
            for (int f = 0; f < NF; f++) { float v = row[f]; s += v * v; }
            g_f2n[idx] = s;
        }
    } else {
        const int ln = tid / MM;
        const int i  = tid - ln * MM;
        const int n  = (blk - ADJ_BLOCK0) * NPB + ln;
        const bool ok = (n < NN) && (ln < NPB);

        if (ok) {
            const int* dstn = dst + (size_t)n * DEG;
            int u = (i == 0) ? n : dstn[i - 1];
            g_nbrs[n * MM + i] = u;

            const int* dstu = dst + (size_t)u * DEG;
            int du[DEG];
            #pragma unroll
            for (int e = 0; e < DEG; e++) du[e] = dstu[e];
            int dn[DEG];
            #pragma unroll
            for (int e = 0; e < DEG; e++) dn[e] = dstn[e];

            unsigned bits = 0;
            #pragma unroll
            for (int j = 0; j < MM; j++) {
                int v = (j == 0) ? n : dn[j - 1];
                bool hit = false;
                #pragma unroll
                for (int e = 0; e < DEG; e++) hit |= (du[e] == v);
                bits |= (unsigned)hit << j;
            }
            sB[ln][i] = bits;
        }
        __syncthreads();
        if (ok) {
            unsigned mk = sB[ln][i];
            #pragma unroll
            for (int j = 0; j < MM; j++)
                mk |= ((sB[ln][j] >> i) & 1u) << j;
            g_mask[n * MM + i] = mk;
        }
    }
}

// ---------------- main: 10 mirror-descent iters + q ----------------
__global__ void __launch_bounds__(272, 3)
k_main(const float* __restrict__ C2g, float* __restrict__ out) {
    __shared__ __align__(16) float sT [NT][MM][MTP];
    __shared__ __align__(16) float sW [NT][MM][MTP];   // cY * C2 . T_b for listed pairs
    __shared__ __align__(16) float sC2 [NT][MT][MTP];
    __shared__ __align__(16) float sq [NT][MTP];
    __shared__ __align__(16) float sU [NT][MTP];       // cY*W0 - cA*constC2   (m>=1)
    __shared__ __align__(16) float sU0[NT][MTP];       // cY*(Zq + c00w*W0) - cA*constC2 (m==0)
    __shared__ float sc00[NT];
    __shared__ int   sColMask[NT];
    __shared__ int   sList[NT * MM];
    __shared__ int   sLn;

    const int tid = threadIdx.x;
    const int n   = blockIdx.x;
    const int k   = tid / MM;
    const int m   = tid - k * MM;

    // cooperative load of C2 into padded smem
    for (int idx = tid; idx < NT * MT * MTP; idx += 272) {
        int kk = idx / (MT * MTP);
        int r  = idx - kk * MT * MTP;
        int s  = r / MTP;
        int t  = r - s * MTP;
        ((float*)sC2)[idx] = (t < MT) ? C2g[(kk * MT + s) * MT + t] : 0.f;
    }
    if (tid < NT) sColMask[tid] = 0;

    const float cA = g_consts[0];
    const float cY = g_consts[1];
    const float cM = g_consts[2];

    // per-thread t-varying cost term: basec[t] = cM*(f2n[kt] - 2*dot)
    const int u = g_nbrs[n * MM + m];
    float basec[MT];
    {
        const float2* drow = (const float2*)(g_D + (size_t)u * NKT + k * MT);
        const float2* frow = (const float2*)(g_f2n + k * MT);
        #pragma unroll
        for (int h = 0; h < 5; h++) {
            float2 v = __ldg(drow + h);
            float2 f = frow[h];
            basec[2*h]   = cM * (f.x - 2.0f * v.x);
            basec[2*h+1] = cM * (f.y - 2.0f * v.y);
        }
    }

    const unsigned mask = g_mask[n * MM + m];
    const unsigned resmask = (m == 0) ? 0u : (mask & ~1u);
    if (m == 0) sc00[k] = (mask & 1u) ? 0.f : -1.f;   // C1[0,0] - 1

    __syncthreads();
    if (resmask) atomicOr(&sColMask[k], (int)resmask);
    __syncthreads();
    if (tid == 0) {
        int L = 0;
        for (int kk = 0; kk < NT; kk++) {
            unsigned cm = (unsigned)sColMask[kk];
            while (cm) { int b = __ffs(cm) - 1; cm &= cm - 1; sList[L++] = (kk << 5) | b; }
        }
        sLn = L;
    }
    __syncthreads();
    const int L10 = 10 * sLn;

    // persistent register copy of this lane's C2 row (m<10 lanes only use it)
    float cr[MT];
    {
        const float* crp = &sC2[k][(m < MT) ? m : 0][0];
        float4 c0 = *(const float4*)crp;
        float4 c1 = *(const float4*)(crp + 4);
        float2 c2 = *(const float2*)(crp + 8);
        cr[0]=c0.x; cr[1]=c0.y; cr[2]=c0.z; cr[3]=c0.w;
        cr[4]=c1.x; cr[5]=c1.y; cr[6]=c1.z; cr[7]=c1.w;
        cr[8]=c2.x; cr[9]=c2.y;
    }

    float lt[MT];
    #pragma unroll
    for (int t = 0; t < MT; t++) lt[t] = 0.f;
    float e[MT];
    float w0own = 0.f;

    #pragma unroll 1
    for (int it = 0; it < 10; it++) {
        // softmax row in registers; T = p * softmax
        float mx = lt[0];
        #pragma unroll
        for (int t = 1; t < MT; t++) mx = fmaxf(mx, lt[t]);
        float ssum = 0.f;
        #pragma unroll
        for (int t = 0; t < MT; t++) { e[t] = __expf(lt[t] - mx); ssum += e[t]; }
        float pr = (1.0f / MM) / ssum;
        #pragma unroll
        for (int t = 0; t < MT; t++) e[t] *= pr;

        float* Trow = &sT[k][m][0];
        ((float4*)Trow)[0] = make_float4(e[0], e[1], e[2], e[3]);
        ((float4*)Trow)[1] = make_float4(e[4], e[5], e[6], e[7]);
        ((float2*)Trow)[4] = make_float2(e[8], e[9]);
        __syncthreads();   // A

        // lanes m<10: q column sum + W0[m] = cr . T0  (T0 row is broadcast-cheap)
        if (m < MT) {
            float qv = 0.f;
            #pragma unroll
            for (int b = 0; b < MM; b++) qv += sT[k][b][m];
            sq[k][m] = qv;

            const float* t0p = &sT[k][0][0];
            float4 a0 = *(const float4*)t0p;
            float4 a1 = *(const float4*)(t0p + 4);
            float2 a2 = *(const float2*)(t0p + 8);
            w0own = cr[0]*a0.x + cr[1]*a0.y + cr[2]*a0.z + cr[3]*a0.w
                  + cr[4]*a1.x + cr[5]*a1.y + cr[6]*a1.z + cr[7]*a1.w
                  + cr[8]*a2.x + cr[9]*a2.y;
        }
        // worklist: residual W_b = cY * C2 . T_b, 10-lane parallel per pair
        for (int idx = tid; idx < L10; idx += 272) {
            int p = idx / 10;
            int s = idx - p * 10;
            int ent = sList[p];
            int kk = ent >> 5, b = ent & 31;
            sW[kk][b][s] = cY * dot10p(&sC2[kk][s][0], &sT[kk][b][0]);
        }
        __syncthreads();   // B

        // lanes m<10: fused Zq = cr.q and constC2 = cr^2.q from the q row (broadcast)
        if (m < MT) {
            const float* qp = &sq[k][0];
            float4 qa = *(const float4*)qp;
            float4 qb = *(const float4*)(qp + 4);
            float2 qc = *(const float2*)(qp + 8);
            float q0=qa.x, q1=qa.y, q2=qa.z, q3=qa.w;
            float q4=qb.x, q5=qb.y, q6=qb.z, q7=qb.w;
            float q8=qc.x, q9=qc.y;
            float zq = 0.f, cc = 0.f;
            float t1;
            t1 = cr[0]*q0; zq += t1; cc = fmaf(t1, cr[0], cc);
            t1 = cr[1]*q1; zq += t1; cc = fmaf(t1, cr[1], cc);
            t1 = cr[2]*q2; zq += t1; cc = fmaf(t1, cr[2], cc);
            t1 = cr[3]*q3; zq += t1; cc = fmaf(t1, cr[3], cc);
            t1 = cr[4]*q4; zq += t1; cc = fmaf(t1, cr[4], cc);
            t1 = cr[5]*q5; zq += t1; cc = fmaf(t1, cr[5], cc);
            t1 = cr[6]*q6; zq += t1; cc = fmaf(t1, cr[6], cc);
            t1 = cr[7]*q7; zq += t1; cc = fmaf(t1, cr[7], cc);
            t1 = cr[8]*q8; zq += t1; cc = fmaf(t1, cr[8], cc);
            t1 = cr[9]*q9; zq += t1; cc = fmaf(t1, cr[9], cc);
            float gcs = cA * cc;
            sU [k][m] = cY * w0own - gcs;
            sU0[k][m] = cY * fmaf(sc00[k], w0own, zq) - gcs;
        }
        __syncthreads();   // C

        // update: lt[s] += U[s] - basec[s] (+ rare residual rows)
        const float* Ur = (m == 0) ? &sU0[k][0] : &sU[k][0];
        float4 u0 = *(const float4*)Ur;
        float4 u1 = *(const float4*)(Ur + 4);
        float2 u2 = *(const float2*)(Ur + 8);
        lt[0] += u0.x - basec[0]; lt[1] += u0.y - basec[1];
        lt[2] += u0.z - basec[2]; lt[3] += u0.w - basec[3];
        lt[4] += u1.x - basec[4]; lt[5] += u1.y - basec[5];
        lt[6] += u1.z - basec[6]; lt[7] += u1.w - basec[7];
        lt[8] += u2.x - basec[8]; lt[9] += u2.y - basec[9];

        unsigned rm = resmask;
        while (rm) {
            int b = __ffs(rm) - 1; rm &= rm - 1;
            const float* Wr = &sW[k][b][0];
            float4 w0v = *(const float4*)Wr;
            float4 w1v = *(const float4*)(Wr + 4);
            float2 w2v = *(const float2*)(Wr + 8);
            lt[0] += w0v.x; lt[1] += w0v.y; lt[2] += w0v.z; lt[3] += w0v.w;
            lt[4] += w1v.x; lt[5] += w1v.y; lt[6] += w1v.z; lt[7] += w1v.w;
            lt[8] += w2v.x; lt[9] += w2v.y;
        }
    }

    // final marginal q from one more softmax
    {
        float mx = lt[0];
        #pragma unroll
        for (int t = 1; t < MT; t++) mx = fmaxf(mx, lt[t]);
        float ssum = 0.f;
        #pragma unroll
        for (int t = 0; t < MT; t++) { e[t] = __expf(lt[t] - mx); ssum += e[t]; }
        float pr = (1.0f / MM) / ssum;
        #pragma unroll
        for (int t = 0; t < MT; t++) e[t] *= pr;
        float* Trow = &sT[k][m][0];
        ((float4*)Trow)[0] = make_float4(e[0], e[1], e[2], e[3]);
        ((float4*)Trow)[1] = make_float4(e[4], e[5], e[6], e[7]);
        ((float2*)Trow)[4] = make_float2(e[8], e[9]);
        __syncthreads();
        if (m < MT) {
            float qv = 0.f;
            #pragma unroll
            for (int b = 0; b < MM; b++) qv += sT[k][b][m];
            out[(size_t)n * NKT + k * MT + m] = qv;
        }
    }
}

// ---------------- launch ----------------
extern "C" void kernel_launch(void* const* d_in, const int* in_sizes, int n_in,
                              void* d_out, int out_size) {
    const float* x      = (const float*)d_in[0];
    const int*   eidx   = (const int*)d_in[1];
    const float* C2g    = (const float*)d_in[2];
    const float* F2     = (const float*)d_in[3];
    const float* alpha0 = (const float*)d_in[4];
    float* out = (float*)d_out;

    const int* dst = eidx + NN * DEG;   // row 1 of edge_index

    k_prep<<<PREP_BLOCKS, 272>>>(x, F2, alpha0, dst);
    k_main<<<NN, 272>>>(C2g, out);
}

// round 9
// speedup vs baseline: 8.0734x; 1.0673x over previous
#include <cuda_runtime.h>
#include <cuda_bf16.h>

#define NN    6000
#define DEG   16
#define MM    17      // DEG+1
#define NT    16
#define MT    10
#define MTP   12      // padded row (floats)
#define NF    128
#define NKT   (NT*MT) // 160
#define REGc  0.1f

#define NTB   8                       // templates per main block
#define TPB   (NTB * MM)              // 136 threads

#define GEMM_BLOCKS   ((NN + 63) / 64)          // 94
#define SETUP_BLOCK   GEMM_BLOCKS               // 94
#define ADJ_BLOCK0    (GEMM_BLOCKS + 1)         // 95
#define NPB           16
#define ADJ_BLOCKS    ((NN + NPB - 1) / NPB)    // 375
#define PREP_BLOCKS   (ADJ_BLOCK0 + ADJ_BLOCKS) // 470

// ---------------- device scratch (no cudaMalloc allowed) ----------------
__device__ int      g_nbrs[NN * MM];
__device__ unsigned g_mask[NN * MM];
__device__ float    g_f2n[NKT];
__device__ float    g_consts[3];     // cA = 2a/REG, cY = 4a/REG, cM = (1-a)/REG
__device__ float    g_D[NN * NKT];   // raw dot:  x[u] . F2[kt]

// packed f32x2 dot over 10 elements (both operands 16B-aligned smem rows)
__device__ __forceinline__ float dot10p(const float* __restrict__ a,
                                        const float* __restrict__ b) {
    const ulonglong2* A = (const ulonglong2*)a;
    const ulonglong2* B = (const ulonglong2*)b;
    ulonglong2 A0 = A[0], A1 = A[1];
    ulonglong2 B0 = B[0], B1 = B[1];
    unsigned long long a2 = *(const unsigned long long*)(a + 8);
    unsigned long long b2 = *(const unsigned long long*)(b + 8);
    unsigned long long acc;
    asm("mul.rn.f32x2 %0, %1, %2;"     : "=l"(acc) : "l"(A0.x), "l"(B0.x));
    asm("fma.rn.f32x2 %0, %1, %2, %0;" : "+l"(acc) : "l"(A0.y), "l"(B0.y));
    asm("fma.rn.f32x2 %0, %1, %2, %0;" : "+l"(acc) : "l"(A1.x), "l"(B1.x));
    asm("fma.rn.f32x2 %0, %1, %2, %0;" : "+l"(acc) : "l"(A1.y), "l"(B1.y));
    asm("fma.rn.f32x2 %0, %1, %2, %0;" : "+l"(acc) : "l"(a2),   "l"(b2));
    unsigned lo, hi;
    asm("mov.b64 {%0,%1}, %2;" : "=r"(lo), "=r"(hi) : "l"(acc));
    return __uint_as_float(lo) + __uint_as_float(hi);
}

// ---------------- fused prologue: setup | gemm | adjacency ----------------
__global__ void __launch_bounds__(272, 3)
k_prep(const float* __restrict__ x, const float* __restrict__ F2,
       const float* __restrict__ alpha0, const int* __restrict__ dst) {
    __shared__ float sX[32][65];
    __shared__ float sF[32][161];
    __shared__ unsigned sB[NPB][MM];

    const int tid = threadIdx.x;
    const int blk = blockIdx.x;

    if (blk < GEMM_BLOCKS) {
        const int tr = tid & 15;
        const int tc = (tid >> 4) & 15;
        const bool act = (tid < 256);
        const int r0 = blk * 64;

        float acc[4][10];
        #pragma unroll
        for (int i = 0; i < 4; i++)
            #pragma unroll
            for (int j = 0; j < 10; j++) acc[i][j] = 0.f;

        for (int k0 = 0; k0 < NF; k0 += 32) {
            __syncthreads();
            for (int idx = tid; idx < 512; idx += 272) {
                int rr = idx >> 3, c4 = idx & 7;
                int gr = r0 + rr;
                float4 v = (gr < NN) ? __ldg((const float4*)(x + (size_t)gr * NF + k0) + c4)
                                     : make_float4(0.f, 0.f, 0.f, 0.f);
                sX[c4*4+0][rr] = v.x; sX[c4*4+1][rr] = v.y;
                sX[c4*4+2][rr] = v.z; sX[c4*4+3][rr] = v.w;
            }
            for (int idx = tid; idx < 1280; idx += 272) {
                int cc = idx >> 3, c4 = idx & 7;
                float4 v = __ldg((const float4*)(F2 + (size_t)cc * NF + k0) + c4);
                sF[c4*4+0][cc] = v.x; sF[c4*4+1][cc] = v.y;
                sF[c4*4+2][cc] = v.z; sF[c4*4+3][cc] = v.w;
            }
            __syncthreads();

            if (act) {
                #pragma unroll 4
                for (int kk = 0; kk < 32; kk++) {
                    float b[10];
                    #pragma unroll
                    for (int j = 0; j < 10; j++) b[j] = sF[kk][tc*10 + j];
                    #pragma unroll
                    for (int i = 0; i < 4; i++) {
                        float a = sX[kk][tr + 16*i];
                        #pragma unroll
                        for (int j = 0; j < 10; j++) acc[i][j] = fmaf(a, b[j], acc[i][j]);
                    }
                }
            }
        }

        if (act) {
            #pragma unroll
            for (int i = 0; i < 4; i++) {
                int r = r0 + tr + 16*i;
                if (r < NN) {
                    float* drow = g_D + (size_t)r * NKT + tc*10;
                    #pragma unroll
                    for (int j = 0; j < 10; j++) drow[j] = acc[i][j];
                }
            }
        }
    } else if (blk == SETUP_BLOCK) {
        if (tid == 0) {
            float a0 = alpha0[0];
            float alpha = 1.0f / (1.0f + __expf(-a0));
            g_consts[0] = 2.0f * alpha / REGc;
            g_consts[1] = 4.0f * alpha / REGc;
            g_consts[2] = (1.0f - alpha) / REGc;
        }
        for (int idx = tid; idx < NKT; idx += 272) {
            const float* row = F2 + (size_t)idx * NF;
            float s = 0.f;
            #pragma unroll 8
            for (int f = 0; f < NF; f++) { float v = row[f]; s += v * v; }
            g_f2n[idx] = s;
        }
    } else {
        const int ln = tid / MM;
        const int i  = tid - ln * MM;
        const int n  = (blk - ADJ_BLOCK0) * NPB + ln;
        const bool ok = (n < NN) && (ln < NPB);

        if (ok) {
            const int* dstn = dst + (size_t)n * DEG;
            int u = (i == 0) ? n : dstn[i - 1];
            g_nbrs[n * MM + i] = u;

            const int* dstu = dst + (size_t)u * DEG;
            int du[DEG];
            #pragma unroll
            for (int e = 0; e < DEG; e++) du[e] = dstu[e];
            int dn[DEG];
            #pragma unroll
            for (int e = 0; e < DEG; e++) dn[e] = dstn[e];

            unsigned bits = 0;
            #pragma unroll
            for (int j = 0; j < MM; j++) {
                int v = (j == 0) ? n : dn[j - 1];
                bool hit = false;
                #pragma unroll
                for (int e = 0; e < DEG; e++) hit |= (du[e] == v);
                bits |= (unsigned)hit << j;
            }
            sB[ln][i] = bits;
        }
        __syncthreads();
        if (ok) {
            unsigned mk = sB[ln][i];
            #pragma unroll
            for (int j = 0; j < MM; j++)
                mk |= ((sB[ln][j] >> i) & 1u) << j;
            g_mask[n * MM + i] = mk;
        }
    }
}

// ---------------- main: peel + 9 mirror-descent iters + q ----------------
// block handles 8 templates of one node: blockIdx = n*2 + half
__global__ void __launch_bounds__(TPB, 6)
k_main(const float* __restrict__ C2g, float* __restrict__ out) {
    __shared__ __align__(16) float sT [NTB][MM][MTP];
    __shared__ __align__(16) float sW [NTB][MM][MTP];
    __shared__ __align__(16) float sC2 [NTB][MT][MTP];
    __shared__ __align__(16) float sq  [NTB][MTP];
    __shared__ __align__(16) float sU  [NTB][MTP];
    __shared__ __align__(16) float sU0 [NTB][MTP];
    __shared__ __align__(16) float sRS [NTB][MTP];
    __shared__ __align__(16) float sRS2[NTB][MTP];
    __shared__ float sc00[NTB];
    __shared__ int   sColMask[NTB];
    __shared__ int   sList[NTB * MM];
    __shared__ int   sLn;

    const int tid = threadIdx.x;
    const int bid = blockIdx.x;
    const int n   = bid >> 1;
    const int kh  = (bid & 1) * NTB;
    const int k   = tid / MM;
    const int m   = tid - k * MM;
    const int kg  = kh + k;

    // cooperative load of this block's 8 C2 matrices
    for (int idx = tid; idx < NTB * MT * MTP; idx += TPB) {
        int kk = idx / (MT * MTP);
        int r  = idx - kk * (MT * MTP);
        int s  = r / MTP;
        int t  = r - s * MTP;
        ((float*)sC2)[idx] = (t < MT) ? C2g[((kh + kk) * MT + s) * MT + t] : 0.f;
    }
    if (tid < NTB) sColMask[tid] = 0;

    const float cA = g_consts[0];
    const float cY = g_consts[1];
    const float cM = g_consts[2];

    // per-thread t-varying cost term: basec[t] = cM*(f2n[kt] - 2*dot)
    const int u = g_nbrs[n * MM + m];
    float basec[MT];
    {
        const float2* drow = (const float2*)(g_D + (size_t)u * NKT + kg * MT);
        const float2* frow = (const float2*)(g_f2n + kg * MT);
        #pragma unroll
        for (int h = 0; h < 5; h++) {
            float2 v = __ldg(drow + h);
            float2 f = frow[h];
            basec[2*h]   = cM * (f.x - 2.0f * v.x);
            basec[2*h+1] = cM * (f.y - 2.0f * v.y);
        }
    }

    const unsigned mask = g_mask[n * MM + m];
    const unsigned resmask = (m == 0) ? 0u : (mask & ~1u);
    const int nres = __popc(resmask);
    const float c00w = (mask & 1u) ? 0.f : -1.f;   // C1[0,0] - 1 (valid for m==0 use)
    if (m == 0) sc00[k] = c00w;

    __syncthreads();   // C2 + colmask-zero ready

    // persistent register copy of this lane's C2 row; publish rowsums
    float cr[MT];
    {
        const float* crp = &sC2[k][(m < MT) ? m : 0][0];
        float4 c0 = *(const float4*)crp;
        float4 c1 = *(const float4*)(crp + 4);
        float2 c2 = *(const float2*)(crp + 8);
        cr[0]=c0.x; cr[1]=c0.y; cr[2]=c0.z; cr[3]=c0.w;
        cr[4]=c1.x; cr[5]=c1.y; cr[6]=c1.z; cr[7]=c1.w;
        cr[8]=c2.x; cr[9]=c2.y;
    }
    if (m < MT) {
        float rs = 0.f, rs2 = 0.f;
        #pragma unroll
        for (int t = 0; t < MT; t++) { rs += cr[t]; rs2 = fmaf(cr[t], cr[t], rs2); }
        sRS [k][m] = rs;
        sRS2[k][m] = rs2;
    }
    if (resmask) atomicOr(&sColMask[k], (int)resmask);
    __syncthreads();

    if (tid == 0) {
        int L = 0;
        for (int kk = 0; kk < NTB; kk++) {
            unsigned cm = (unsigned)sColMask[kk];
            while (cm) { int b = __ffs(cm) - 1; cm &= cm - 1; sList[L++] = (kk << 5) | b; }
        }
        sLn = L;
    }
    __syncthreads();
    const int L10 = 10 * sLn;

    // precompute own worklist task (common case: <=1 per thread)
    int offA = 0, offB = 0, offW = 0;
    const bool hasTask = (tid < L10);
    if (hasTask) {
        int p = tid / 10;
        int s = tid - p * 10;
        int ent = sList[p];
        int kk = ent >> 5, b = ent & 31;
        offA = (kk * MT + s) * MTP;
        offB = (kk * MM + b) * MTP;
        offW = offB + s;
    }

    // ---- peeled iteration 0 (T uniform = 1/170) ----
    float lt[MT];
    {
        const float E0 = 1.0f / 170.0f;
        float f = (m == 0) ? (0.1f + c00w * E0) : (E0 * (1.0f + (float)nres));
        const float g2 = 0.1f * cA;
        const float* rsp  = &sRS [k][0];
        const float* rs2p = &sRS2[k][0];
        float4 ra = *(const float4*)rsp,       rb = *(const float4*)(rsp + 4);
        float2 rc = *(const float2*)(rsp + 8);
        float4 sa = *(const float4*)rs2p,      sb = *(const float4*)(rs2p + 4);
        float2 sc = *(const float2*)(rs2p + 8);
        float cf = cY * f;
        lt[0] = cf*ra.x - g2*sa.x - basec[0]; lt[1] = cf*ra.y - g2*sa.y - basec[1];
        lt[2] = cf*ra.z - g2*sa.z - basec[2]; lt[3] = cf*ra.w - g2*sa.w - basec[3];
        lt[4] = cf*rb.x - g2*sb.x - basec[4]; lt[5] = cf*rb.y - g2*sb.y - basec[5];
        lt[6] = cf*rb.z - g2*sb.z - basec[6]; lt[7] = cf*rb.w - g2*sb.w - basec[7];
        lt[8] = cf*rc.x - g2*sc.x - basec[8]; lt[9] = cf*rc.y - g2*sc.y - basec[9];
    }

    float e[MT];
    float w0own = 0.f;

    #pragma unroll 1
    for (int it = 1; it < 10; it++) {
        // softmax row in registers; T = p * softmax
        float mx = lt[0];
        #pragma unroll
        for (int t = 1; t < MT; t++) mx = fmaxf(mx, lt[t]);
        float ssum = 0.f;
        #pragma unroll
        for (int t = 0; t < MT; t++) { e[t] = __expf(lt[t] - mx); ssum += e[t]; }
        float pr = (1.0f / MM) / ssum;
        #pragma unroll
        for (int t = 0; t < MT; t++) e[t] *= pr;

        float* Trow = &sT[k][m][0];
        ((float4*)Trow)[0] = make_float4(e[0], e[1], e[2], e[3]);
        ((float4*)Trow)[1] = make_float4(e[4], e[5], e[6], e[7]);
        ((float2*)Trow)[4] = make_float2(e[8], e[9]);
        __syncthreads();   // A

        // lanes m<10: q column sum + W0[m] = cr . T0
        if (m < MT) {
            float qv = 0.f;
            #pragma unroll
            for (int b = 0; b < MM; b++) qv += sT[k][b][m];
            sq[k][m] = qv;

            const float* t0p = &sT[k][0][0];
            float4 a0 = *(const float4*)t0p;
            float4 a1 = *(const float4*)(t0p + 4);
            float2 a2 = *(const float2*)(t0p + 8);
            w0own = cr[0]*a0.x + cr[1]*a0.y + cr[2]*a0.z + cr[3]*a0.w
                  + cr[4]*a1.x + cr[5]*a1.y + cr[6]*a1.z + cr[7]*a1.w
                  + cr[8]*a2.x + cr[9]*a2.y;
        }
        // worklist: own precomputed task + rare overflow
        if (hasTask)
            ((float*)sW)[offW] = cY * dot10p(&((const float*)sC2)[offA],
                                            &((const float*)sT)[offB]);
        for (int idx = tid + TPB; idx < L10; idx += TPB) {
            int p = idx / 10;
            int s = idx - p * 10;
            int ent = sList[p];
            int kk = ent >> 5, b = ent & 31;
            sW[kk][b][s] = cY * dot10p(&sC2[kk][s][0], &sT[kk][b][0]);
        }
        __syncthreads();   // B

        // lanes m<10: fused Zq = cr.q and constC2 = cr^2.q
        if (m < MT) {
            const float* qp = &sq[k][0];
            float4 qa = *(const float4*)qp;
            float4 qb = *(const float4*)(qp + 4);
            float2 qc = *(const float2*)(qp + 8);
            float q0=qa.x, q1=qa.y, q2=qa.z, q3=qa.w;
            float q4=qb.x, q5=qb.y, q6=qb.z, q7=qb.w;
            float q8=qc.x, q9=qc.y;
            float zq = 0.f, cc = 0.f;
            float t1;
            t1 = cr[0]*q0; zq += t1; cc = fmaf(t1, cr[0], cc);
            t1 = cr[1]*q1; zq += t1; cc = fmaf(t1, cr[1], cc);
            t1 = cr[2]*q2; zq += t1; cc = fmaf(t1, cr[2], cc);
            t1 = cr[3]*q3; zq += t1; cc = fmaf(t1, cr[3], cc);
            t1 = cr[4]*q4; zq += t1; cc = fmaf(t1, cr[4], cc);
            t1 = cr[5]*q5; zq += t1; cc = fmaf(t1, cr[5], cc);
            t1 = cr[6]*q6; zq += t1; cc = fmaf(t1, cr[6], cc);
            t1 = cr[7]*q7; zq += t1; cc = fmaf(t1, cr[7], cc);
            t1 = cr[8]*q8; zq += t1; cc = fmaf(t1, cr[8], cc);
            t1 = cr[9]*q9; zq += t1; cc = fmaf(t1, cr[9], cc);
            float gcs = cA * cc;
            sU [k][m] = cY * w0own - gcs;
            sU0[k][m] = cY * fmaf(sc00[k], w0own, zq) - gcs;
        }
        __syncthreads();   // C

        // update: lt[s] += U[s] - basec[s] (+ rare residual rows)
        const float* Ur = (m == 0) ? &sU0[k][0] : &sU[k][0];
        float4 u0 = *(const float4*)Ur;
        float4 u1 = *(const float4*)(Ur + 4);
        float2 u2 = *(const float2*)(Ur + 8);
        lt[0] += u0.x - basec[0]; lt[1] += u0.y - basec[1];
        lt[2] += u0.z - basec[2]; lt[3] += u0.w - basec[3];
        lt[4] += u1.x - basec[4]; lt[5] += u1.y - basec[5];
        lt[6] += u1.z - basec[6]; lt[7] += u1.w - basec[7];
        lt[8] += u2.x - basec[8]; lt[9] += u2.y - basec[9];

        unsigned rm = resmask;
        while (rm) {
            int b = __ffs(rm) - 1; rm &= rm - 1;
            const float* Wr = &sW[k][b][0];
            float4 w0v = *(const float4*)Wr;
            float4 w1v = *(const float4*)(Wr + 4);
            float2 w2v = *(const float2*)(Wr + 8);
            lt[0] += w0v.x; lt[1] += w0v.y; lt[2] += w0v.z; lt[3] += w0v.w;
            lt[4] += w1v.x; lt[5] += w1v.y; lt[6] += w1v.z; lt[7] += w1v.w;
            lt[8] += w2v.x; lt[9] += w2v.y;
        }
    }

    // final marginal q from one more softmax
    {
        float mx = lt[0];
        #pragma unroll
        for (int t = 1; t < MT; t++) mx = fmaxf(mx, lt[t]);
        float ssum = 0.f;
        #pragma unroll
        for (int t = 0; t < MT; t++) { e[t] = __expf(lt[t] - mx); ssum += e[t]; }
        float pr = (1.0f / MM) / ssum;
        #pragma unroll
        for (int t = 0; t < MT; t++) e[t] *= pr;
        float* Trow = &sT[k][m][0];
        ((float4*)Trow)[0] = make_float4(e[0], e[1], e[2], e[3]);
        ((float4*)Trow)[1] = make_float4(e[4], e[5], e[6], e[7]);
        ((float2*)Trow)[4] = make_float2(e[8], e[9]);
        __syncthreads();
        if (m < MT) {
            float qv = 0.f;
            #pragma unroll
            for (int b = 0; b < MM; b++) qv += sT[k][b][m];
            out[(size_t)n * NKT + kg * MT + m] = qv;
        }
    }
}

// ---------------- launch ----------------
extern "C" void kernel_launch(void* const* d_in, const int* in_sizes, int n_in,
                              void* d_out, int out_size) {
    const float* x      = (const float*)d_in[0];
    const int*   eidx   = (const int*)d_in[1];
    const float* C2g    = (const float*)d_in[2];
    const float* F2     = (const float*)d_in[3];
    const float* alpha0 = (const float*)d_in[4];
    float* out = (float*)d_out;

    const int* dst = eidx + NN * DEG;   // row 1 of edge_index

    k_prep<<<PREP_BLOCKS, 272>>>(x, F2, alpha0, dst);
    k_main<<<NN * 2, TPB>>>(C2g, out);
}

// round 10
// speedup vs baseline: 8.9554x; 1.1092x over previous
#include <cuda_runtime.h>
#include <cuda_bf16.h>

#define NN    6000
#define DEG   16
#define MM    17      // DEG+1
#define NT    16
#define MT    10
#define MTP   12      // padded row (floats)
#define NF    128
#define NKT   (NT*MT) // 160
#define REGc  0.1f
#define NWARPS 8
#define TPB_MAIN 256

#define GEMM_BLOCKS   ((NN + 63) / 64)          // 94
#define SETUP_BLOCK   GEMM_BLOCKS               // 94
#define ADJ_BLOCK0    (GEMM_BLOCKS + 1)         // 95
#define NPB           16
#define ADJ_BLOCKS    ((NN + NPB - 1) / NPB)    // 375
#define PREP_BLOCKS   (ADJ_BLOCK0 + ADJ_BLOCKS) // 470

// ---------------- device scratch (no cudaMalloc allowed) ----------------
__device__ int      g_nbrs[NN * MM];
__device__ unsigned g_mask[NN * MM];
__device__ float    g_f2n[NKT];
__device__ float    g_consts[3];     // cA = 2a/REG, cY = 4a/REG, cM = (1-a)/REG
__device__ float    g_D[NN * NKT];   // raw dot:  x[u] . F2[kt]

// packed f32x2 dot over 10 elements (both operands 16B-aligned smem rows)
__device__ __forceinline__ float dot10p(const float* __restrict__ a,
                                        const float* __restrict__ b) {
    const ulonglong2* A = (const ulonglong2*)a;
    const ulonglong2* B = (const ulonglong2*)b;
    ulonglong2 A0 = A[0], A1 = A[1];
    ulonglong2 B0 = B[0], B1 = B[1];
    unsigned long long a2 = *(const unsigned long long*)(a + 8);
    unsigned long long b2 = *(const unsigned long long*)(b + 8);
    unsigned long long acc;
    asm("mul.rn.f32x2 %0, %1, %2;"     : "=l"(acc) : "l"(A0.x), "l"(B0.x));
    asm("fma.rn.f32x2 %0, %1, %2, %0;" : "+l"(acc) : "l"(A0.y), "l"(B0.y));
    asm("fma.rn.f32x2 %0, %1, %2, %0;" : "+l"(acc) : "l"(A1.x), "l"(B1.x));
    asm("fma.rn.f32x2 %0, %1, %2, %0;" : "+l"(acc) : "l"(A1.y), "l"(B1.y));
    asm("fma.rn.f32x2 %0, %1, %2, %0;" : "+l"(acc) : "l"(a2),   "l"(b2));
    unsigned lo, hi;
    asm("mov.b64 {%0,%1}, %2;" : "=r"(lo), "=r"(hi) : "l"(acc));
    return __uint_as_float(lo) + __uint_as_float(hi);
}

// ---------------- fused prologue: setup | gemm | adjacency ----------------
__global__ void __launch_bounds__(272, 3)
k_prep(const float* __restrict__ x, const float* __restrict__ F2,
       const float* __restrict__ alpha0, const int* __restrict__ dst) {
    __shared__ float sX[32][65];
    __shared__ float sF[32][161];
    __shared__ unsigned sB[NPB][MM];

    const int tid = threadIdx.x;
    const int blk = blockIdx.x;

    if (blk < GEMM_BLOCKS) {
        const int tr = tid & 15;
        const int tc = (tid >> 4) & 15;
        const bool act = (tid < 256);
        const int r0 = blk * 64;

        float acc[4][10];
        #pragma unroll
        for (int i = 0; i < 4; i++)
            #pragma unroll
            for (int j = 0; j < 10; j++) acc[i][j] = 0.f;

        for (int k0 = 0; k0 < NF; k0 += 32) {
            __syncthreads();
            for (int idx = tid; idx < 512; idx += 272) {
                int rr = idx >> 3, c4 = idx & 7;
                int gr = r0 + rr;
                float4 v = (gr < NN) ? __ldg((const float4*)(x + (size_t)gr * NF + k0) + c4)
                                     : make_float4(0.f, 0.f, 0.f, 0.f);
                sX[c4*4+0][rr] = v.x; sX[c4*4+1][rr] = v.y;
                sX[c4*4+2][rr] = v.z; sX[c4*4+3][rr] = v.w;
            }
            for (int idx = tid; idx < 1280; idx += 272) {
                int cc = idx >> 3, c4 = idx & 7;
                float4 v = __ldg((const float4*)(F2 + (size_t)cc * NF + k0) + c4);
                sF[c4*4+0][cc] = v.x; sF[c4*4+1][cc] = v.y;
                sF[c4*4+2][cc] = v.z; sF[c4*4+3][cc] = v.w;
            }
            __syncthreads();

            if (act) {
                #pragma unroll 4
                for (int kk = 0; kk < 32; kk++) {
                    float b[10];
                    #pragma unroll
                    for (int j = 0; j < 10; j++) b[j] = sF[kk][tc*10 + j];
                    #pragma unroll
                    for (int i = 0; i < 4; i++) {
                        float a = sX[kk][tr + 16*i];
                        #pragma unroll
                        for (int j = 0; j < 10; j++) acc[i][j] = fmaf(a, b[j], acc[i][j]);
                    }
                }
            }
        }

        if (act) {
            #pragma unroll
            for (int i = 0; i < 4; i++) {
                int r = r0 + tr + 16*i;
                if (r < NN) {
                    float* drow = g_D + (size_t)r * NKT + tc*10;
                    #pragma unroll
                    for (int j = 0; j < 10; j++) drow[j] = acc[i][j];
                }
            }
        }
    } else if (blk == SETUP_BLOCK) {
        if (tid == 0) {
            float a0 = alpha0[0];
            float alpha = 1.0f / (1.0f + __expf(-a0));
            g_consts[0] = 2.0f * alpha / REGc;
            g_consts[1] = 4.0f * alpha / REGc;
            g_consts[2] = (1.0f - alpha) / REGc;
        }
        for (int idx = tid; idx < NKT; idx += 272) {
            const float* row = F2 + (size_t)idx * NF;
            float s = 0.f;
            #pragma unroll 8
            for (int f = 0; f < NF; f++) { float v = row[f]; s += v * v; }
            g_f2n[idx] = s;
        }
    } else {
        const int ln = tid / MM;
        const int i  = tid - ln * MM;
        const int n  = (blk - ADJ_BLOCK0) * NPB + ln;
        const bool ok = (n < NN) && (ln < NPB);

        if (ok) {
            const int* dstn = dst + (size_t)n * DEG;
            int u = (i == 0) ? n : dstn[i - 1];
            g_nbrs[n * MM + i] = u;

            const int* dstu = dst + (size_t)u * DEG;
            int du[DEG];
            #pragma unroll
            for (int e = 0; e < DEG; e++) du[e] = dstu[e];
            int dn[DEG];
            #pragma unroll
            for (int e = 0; e < DEG; e++) dn[e] = dstn[e];

            unsigned bits = 0;
            #pragma unroll
            for (int j = 0; j < MM; j++) {
                int v = (j == 0) ? n : dn[j - 1];
                bool hit = false;
                #pragma unroll
                for (int e = 0; e < DEG; e++) hit |= (du[e] == v);
                bits |= (unsigned)hit << j;
            }
            sB[ln][i] = bits;
        }
        __syncthreads();
        if (ok) {
            unsigned mk = sB[ln][i];
            #pragma unroll
            for (int j = 0; j < MM; j++)
                mk |= ((sB[ln][j] >> i) & 1u) << j;
            g_mask[n * MM + i] = mk;
        }
    }
}

// ---------------- main: fully warp-synchronous ----------------
// block = 1 node, 8 warps; warp = 2 templates x 16 rows (+ distributed row 0)
__global__ void __launch_bounds__(TPB_MAIN, 3)
k_main(const float* __restrict__ C2g, float* __restrict__ out) {
    __shared__ __align__(16) float sT [NT][MM][MTP];
    __shared__ __align__(16) float sW [NT][MM][MTP];
    __shared__ __align__(16) float sC2[NT][MT][MTP];
    __shared__ __align__(16) float sq [NT][MTP];
    __shared__ __align__(16) float sU [NT][MTP];
    __shared__ __align__(16) float sRS [NT][MTP];
    __shared__ __align__(16) float sRS2[NT][MTP];
    __shared__ int sList[NWARPS][32];
    __shared__ int sLn[NWARPS];

    const int tid = threadIdx.x;
    const int n   = blockIdx.x;
    const int w   = tid >> 5;
    const int l   = tid & 31;
    const int g   = l >> 4;            // template within warp
    const int j   = l & 15;            // 0..15
    const int kk  = w * 2 + g;         // global template 0..15
    const int r   = j + 1;             // own row 1..16
    const bool sl = (j < MT);          // s-lane (owns output column j)

    const float cA = g_consts[0];
    const float cY = g_consts[1];
    const float cM = g_consts[2];

    // warp-local C2 load (2 templates)
    for (int idx = l; idx < 2 * MT * MTP; idx += 32) {
        int kkk = w*2 + idx / (MT*MTP);
        int rr  = idx % (MT*MTP);
        int s2  = rr / MTP, t2 = rr % MTP;
        sC2[kkk][s2][t2] = (t2 < MT) ? C2g[(kkk*MT + s2)*MT + t2] : 0.f;
    }

    // basec for own row (r)
    const int u = g_nbrs[n*MM + r];
    float basec[MT];
    {
        const float2* drow = (const float2*)(g_D + (size_t)u * NKT + kk * MT);
        const float2* frow = (const float2*)(g_f2n + kk * MT);
        #pragma unroll
        for (int h = 0; h < 5; h++) {
            float2 v = __ldg(drow + h);
            float2 f = frow[h];
            basec[2*h]   = cM * (f.x - 2.0f * v.x);
            basec[2*h+1] = cM * (f.y - 2.0f * v.y);
        }
    }
    // row-0 basec element (s-lanes only)
    float b0 = 0.f;
    if (sl) {
        float d0 = __ldg(g_D + (size_t)n * NKT + kk * MT + j);
        b0 = cM * (g_f2n[kk * MT + j] - 2.0f * d0);
    }

    // masks
    const unsigned mask = g_mask[n*MM + r];
    const unsigned resmask = mask & ~1u;
    const int nres = __popc(resmask);
    unsigned m0 = 0;
    if (j == 0) m0 = g_mask[n*MM];
    m0 = __shfl_sync(0xffffffffu, m0, 0, 16);        // broadcast within half
    const float c00 = (m0 & 1u) ? 0.f : -1.f;        // C1[0,0]-1

    // per-half colmask via shuffle-OR
    unsigned cm = resmask;
    cm |= __shfl_xor_sync(0xffffffffu, cm, 1, 16);
    cm |= __shfl_xor_sync(0xffffffffu, cm, 2, 16);
    cm |= __shfl_xor_sync(0xffffffffu, cm, 4, 16);
    cm |= __shfl_xor_sync(0xffffffffu, cm, 8, 16);
    unsigned cmB = __shfl_sync(0xffffffffu, cm, 16); // half-B colmask
    __syncwarp();
    if (l == 0) {
        int L = 0;
        unsigned ca = cm;
        while (ca) { int b = __ffs(ca)-1; ca &= ca-1; sList[w][L++] = b; }
        unsigned cb = cmB;
        while (cb) { int b = __ffs(cb)-1; cb &= cb-1; sList[w][L++] = 32 | b; }
        sLn[w] = L;
    }
    __syncwarp();
    const int L10 = 10 * sLn[w];
    int offA = 0, offB = 0, offW = 0;
    const bool hasTask = (l < L10);
    if (hasTask) {
        int p = l / 10, s2 = l - p*10;
        int ent = sList[w][p];
        int kt = w*2 + (ent >> 5); int b = ent & 31;
        offA = (kt*MT + s2) * MTP;
        offB = (kt*MM + b) * MTP;
        offW = offB + s2;
    }

    // persistent C2 row for s-lanes; publish rowsums for peel
    float cr[MT];
    {
        const float* crp = &sC2[kk][sl ? j : 0][0];
        float4 c0 = *(const float4*)crp;
        float4 c1 = *(const float4*)(crp + 4);
        float2 c2 = *(const float2*)(crp + 8);
        cr[0]=c0.x; cr[1]=c0.y; cr[2]=c0.z; cr[3]=c0.w;
        cr[4]=c1.x; cr[5]=c1.y; cr[6]=c1.z; cr[7]=c1.w;
        cr[8]=c2.x; cr[9]=c2.y;
    }
    float rsown = 0.f, rs2own = 0.f;
    #pragma unroll
    for (int t = 0; t < MT; t++) { rsown += cr[t]; rs2own = fmaf(cr[t], cr[t], rs2own); }
    if (sl) { sRS[kk][j] = rsown; sRS2[kk][j] = rs2own; }
    __syncwarp();

    // ---- peeled iteration 0 (T uniform = 1/170) ----
    const float E0 = 1.0f / 170.0f;
    const float g2 = 0.1f * cA;
    float lt[MT];
    {
        float cf = cY * (E0 * (1.0f + (float)nres));
        const float* rsp  = &sRS [kk][0];
        const float* rs2p = &sRS2[kk][0];
        float4 ra = *(const float4*)rsp,  rb = *(const float4*)(rsp + 4);
        float2 rc = *(const float2*)(rsp + 8);
        float4 sa = *(const float4*)rs2p, sb = *(const float4*)(rs2p + 4);
        float2 sc = *(const float2*)(rs2p + 8);
        lt[0] = cf*ra.x - g2*sa.x - basec[0]; lt[1] = cf*ra.y - g2*sa.y - basec[1];
        lt[2] = cf*ra.z - g2*sa.z - basec[2]; lt[3] = cf*ra.w - g2*sa.w - basec[3];
        lt[4] = cf*rb.x - g2*sb.x - basec[4]; lt[5] = cf*rb.y - g2*sb.y - basec[5];
        lt[6] = cf*rb.z - g2*sb.z - basec[6]; lt[7] = cf*rb.w - g2*sb.w - basec[7];
        lt[8] = cf*rc.x - g2*sc.x - basec[8]; lt[9] = cf*rc.y - g2*sc.y - basec[9];
    }
    float lt0 = 0.f;
    if (sl) lt0 = cY * (0.1f + c00 * E0) * rsown - g2 * rs2own - b0;

    float w0own = 0.f;

    #pragma unroll 1
    for (int it = 1; it <= 10; it++) {
        // phase 1: softmax own row + store; distributed row-0 softmax
        {
            float mx = lt[0];
            #pragma unroll
            for (int t = 1; t < MT; t++) mx = fmaxf(mx, lt[t]);
            float e[MT];
            float ssum = 0.f;
            #pragma unroll
            for (int t = 0; t < MT; t++) { e[t] = __expf(lt[t] - mx); ssum += e[t]; }
            float pr = (1.0f / MM) / ssum;
            #pragma unroll
            for (int t = 0; t < MT; t++) e[t] *= pr;
            float* Trow = &sT[kk][r][0];
            ((float4*)Trow)[0] = make_float4(e[0], e[1], e[2], e[3]);
            ((float4*)Trow)[1] = make_float4(e[4], e[5], e[6], e[7]);
            ((float2*)Trow)[4] = make_float2(e[8], e[9]);
        }
        {
            float v0 = sl ? lt0 : -3.0e38f;
            float mx0 = v0;
            mx0 = fmaxf(mx0, __shfl_xor_sync(0xffffffffu, mx0, 1, 16));
            mx0 = fmaxf(mx0, __shfl_xor_sync(0xffffffffu, mx0, 2, 16));
            mx0 = fmaxf(mx0, __shfl_xor_sync(0xffffffffu, mx0, 4, 16));
            mx0 = fmaxf(mx0, __shfl_xor_sync(0xffffffffu, mx0, 8, 16));
            float e0 = sl ? __expf(lt0 - mx0) : 0.f;
            float s0 = e0;
            s0 += __shfl_xor_sync(0xffffffffu, s0, 1, 16);
            s0 += __shfl_xor_sync(0xffffffffu, s0, 2, 16);
            s0 += __shfl_xor_sync(0xffffffffu, s0, 4, 16);
            s0 += __shfl_xor_sync(0xffffffffu, s0, 8, 16);
            if (sl) sT[kk][0][j] = e0 * ((1.0f / MM) / s0);
        }
        __syncwarp();

        if (it == 10) break;   // final T stored; epilogue computes q

        // phase 2: colsum + W0 (s-lanes); worklist dots (all lanes)
        if (sl) {
            float qv = 0.f;
            #pragma unroll
            for (int b = 0; b < MM; b++) qv += sT[kk][b][j];
            sq[kk][j] = qv;

            const float* t0p = &sT[kk][0][0];
            float4 a0 = *(const float4*)t0p;
            float4 a1 = *(const float4*)(t0p + 4);
            float2 a2 = *(const float2*)(t0p + 8);
            w0own = cr[0]*a0.x + cr[1]*a0.y + cr[2]*a0.z + cr[3]*a0.w
                  + cr[4]*a1.x + cr[5]*a1.y + cr[6]*a1.z + cr[7]*a1.w
                  + cr[8]*a2.x + cr[9]*a2.y;
        }
        if (hasTask)
            ((float*)sW)[offW] = cY * dot10p(&((const float*)sC2)[offA],
                                            &((const float*)sT)[offB]);
        for (int idx = l + 32; idx < L10; idx += 32) {
            int p = idx / 10, s2 = idx - p*10;
            int ent = sList[w][p];
            int kt = w*2 + (ent >> 5); int b = ent & 31;
            sW[kt][b][s2] = cY * dot10p(&sC2[kt][s2][0], &sT[kt][b][0]);
        }
        __syncwarp();

        // phase 3: s-lanes: Zq/cc fused; publish U; update row-0 logit
        if (sl) {
            const float* qp = &sq[kk][0];
            float4 qa = *(const float4*)qp;
            float4 qb = *(const float4*)(qp + 4);
            float2 qc = *(const float2*)(qp + 8);
            float zq = 0.f, cc = 0.f, t1;
            t1 = cr[0]*qa.x; zq += t1; cc = fmaf(t1, cr[0], cc);
            t1 = cr[1]*qa.y; zq += t1; cc = fmaf(t1, cr[1], cc);
            t1 = cr[2]*qa.z; zq += t1; cc = fmaf(t1, cr[2], cc);
            t1 = cr[3]*qa.w; zq += t1; cc = fmaf(t1, cr[3], cc);
            t1 = cr[4]*qb.x; zq += t1; cc = fmaf(t1, cr[4], cc);
            t1 = cr[5]*qb.y; zq += t1; cc = fmaf(t1, cr[5], cc);
            t1 = cr[6]*qb.z; zq += t1; cc = fmaf(t1, cr[6], cc);
            t1 = cr[7]*qb.w; zq += t1; cc = fmaf(t1, cr[7], cc);
            t1 = cr[8]*qc.x; zq += t1; cc = fmaf(t1, cr[8], cc);
            t1 = cr[9]*qc.y; zq += t1; cc = fmaf(t1, cr[9], cc);
            float gcs = cA * cc;
            sU[kk][j] = cY * w0own - gcs;
            lt0 += cY * fmaf(c00, w0own, zq) - gcs - b0;
        }
        __syncwarp();

        // phase 4: all lanes update own row
        {
            const float* Ur = &sU[kk][0];
            float4 u0 = *(const float4*)Ur;
            float4 u1 = *(const float4*)(Ur + 4);
            float2 u2 = *(const float2*)(Ur + 8);
            lt[0] += u0.x - basec[0]; lt[1] += u0.y - basec[1];
            lt[2] += u0.z - basec[2]; lt[3] += u0.w - basec[3];
            lt[4] += u1.x - basec[4]; lt[5] += u1.y - basec[5];
            lt[6] += u1.z - basec[6]; lt[7] += u1.w - basec[7];
            lt[8] += u2.x - basec[8]; lt[9] += u2.y - basec[9];

            unsigned rm = resmask;
            while (rm) {
                int b = __ffs(rm) - 1; rm &= rm - 1;
                const float* Wr = &sW[kk][b][0];
                float4 w0v = *(const float4*)Wr;
                float4 w1v = *(const float4*)(Wr + 4);
                float2 w2v = *(const float2*)(Wr + 8);
                lt[0] += w0v.x; lt[1] += w0v.y; lt[2] += w0v.z; lt[3] += w0v.w;
                lt[4] += w1v.x; lt[5] += w1v.y; lt[6] += w1v.z; lt[7] += w1v.w;
                lt[8] += w2v.x; lt[9] += w2v.y;
            }
        }
    }

    // epilogue: final marginal q (T already stored at it==10)
    if (sl) {
        float qv = 0.f;
        #pragma unroll
        for (int b = 0; b < MM; b++) qv += sT[kk][b][j];
        out[(size_t)n * NKT + kk * MT + j] = qv;
    }
}

// ---------------- launch ----------------
extern "C" void kernel_launch(void* const* d_in, const int* in_sizes, int n_in,
                              void* d_out, int out_size) {
    const float* x      = (const float*)d_in[0];
    const int*   eidx   = (const int*)d_in[1];
    const float* C2g    = (const float*)d_in[2];
    const float* F2     = (const float*)d_in[3];
    const float* alpha0 = (const float*)d_in[4];
    float* out = (float*)d_out;

    const int* dst = eidx + NN * DEG;   // row 1 of edge_index

    k_prep<<<PREP_BLOCKS, 272>>>(x, F2, alpha0, dst);
    k_main<<<NN, TPB_MAIN>>>(C2g, out);
}

// round 11
// speedup vs baseline: 9.0384x; 1.0093x over previous
#include <cuda_runtime.h>
#include <cuda_bf16.h>

#define NN    6000
#define DEG   16
#define MM    17      // DEG+1
#define NT    16
#define MT    10
#define MTP   12      // padded row (floats)
#define NF    128
#define NKT   (NT*MT) // 160
#define REGc  0.1f
#define NWARPS 8
#define TPB_MAIN 256

#define GEMM_BLOCKS   ((NN + 63) / 64)          // 94
#define SETUP_BLOCK   GEMM_BLOCKS               // 94
#define ADJ_BLOCK0    (GEMM_BLOCKS + 1)         // 95
#define NPB           16
#define ADJ_BLOCKS    ((NN + NPB - 1) / NPB)    // 375
#define PREP_BLOCKS   (ADJ_BLOCK0 + ADJ_BLOCKS) // 470

typedef unsigned long long u64;

// ---------------- device scratch (no cudaMalloc allowed) ----------------
__device__ int      g_nbrs[NN * MM];
__device__ unsigned g_mask[NN * MM];
__device__ float    g_f2n[NKT];
__device__ float    g_consts[3];     // cA = 2a/REG, cY = 4a/REG, cM = (1-a)/REG
__device__ float    g_D[NN * NKT];   // raw dot:  x[u] . F2[kt]

// ---------------- packed f32x2 helpers ----------------
__device__ __forceinline__ u64 pk2(float x, float y) {
    u64 r; asm("mov.b64 %0,{%1,%2};" : "=l"(r) : "f"(x), "f"(y)); return r;
}
__device__ __forceinline__ void up2(u64 v, float& x, float& y) {
    asm("mov.b64 {%0,%1},%2;" : "=f"(x), "=f"(y) : "l"(v));
}
__device__ __forceinline__ u64 add2(u64 a, u64 b) {
    u64 r; asm("add.rn.f32x2 %0,%1,%2;" : "=l"(r) : "l"(a), "l"(b)); return r;
}
__device__ __forceinline__ u64 mul2(u64 a, u64 b) {
    u64 r; asm("mul.rn.f32x2 %0,%1,%2;" : "=l"(r) : "l"(a), "l"(b)); return r;
}
__device__ __forceinline__ u64 fma2(u64 a, u64 b, u64 c) {
    u64 r; asm("fma.rn.f32x2 %0,%1,%2,%3;" : "=l"(r) : "l"(a), "l"(b), "l"(c)); return r;
}
__device__ __forceinline__ float hsum2(u64 v) {
    float x, y; up2(v, x, y); return x + y;
}

// packed f32x2 dot over 10 elements (both operands 16B-aligned smem rows)
__device__ __forceinline__ float dot10p(const float* __restrict__ a,
                                        const float* __restrict__ b) {
    const ulonglong2* A = (const ulonglong2*)a;
    const ulonglong2* B = (const ulonglong2*)b;
    ulonglong2 A0 = A[0], A1 = A[1];
    ulonglong2 B0 = B[0], B1 = B[1];
    u64 a2 = *(const u64*)(a + 8);
    u64 b2 = *(const u64*)(b + 8);
    u64 acc = mul2(A0.x, B0.x);
    acc = fma2(A0.y, B0.y, acc);
    acc = fma2(A1.x, B1.x, acc);
    acc = fma2(A1.y, B1.y, acc);
    acc = fma2(a2,   b2,   acc);
    return hsum2(acc);
}

// ---------------- fused prologue: setup | gemm | adjacency ----------------
__global__ void __launch_bounds__(272, 3)
k_prep(const float* __restrict__ x, const float* __restrict__ F2,
       const float* __restrict__ alpha0, const int* __restrict__ dst) {
    __shared__ float sX[32][65];
    __shared__ float sF[32][161];
    __shared__ unsigned sB[NPB][MM];

    const int tid = threadIdx.x;
    const int blk = blockIdx.x;

    if (blk < GEMM_BLOCKS) {
        const int tr = tid & 15;
        const int tc = (tid >> 4) & 15;
        const bool act = (tid < 256);
        const int r0 = blk * 64;

        float acc[4][10];
        #pragma unroll
        for (int i = 0; i < 4; i++)
            #pragma unroll
            for (int j = 0; j < 10; j++) acc[i][j] = 0.f;

        for (int k0 = 0; k0 < NF; k0 += 32) {
            __syncthreads();
            for (int idx = tid; idx < 512; idx += 272) {
                int rr = idx >> 3, c4 = idx & 7;
                int gr = r0 + rr;
                float4 v = (gr < NN) ? __ldg((const float4*)(x + (size_t)gr * NF + k0) + c4)
                                     : make_float4(0.f, 0.f, 0.f, 0.f);
                sX[c4*4+0][rr] = v.x; sX[c4*4+1][rr] = v.y;
                sX[c4*4+2][rr] = v.z; sX[c4*4+3][rr] = v.w;
            }
            for (int idx = tid; idx < 1280; idx += 272) {
                int cc = idx >> 3, c4 = idx & 7;
                float4 v = __ldg((const float4*)(F2 + (size_t)cc * NF + k0) + c4);
                sF[c4*4+0][cc] = v.x; sF[c4*4+1][cc] = v.y;
                sF[c4*4+2][cc] = v.z; sF[c4*4+3][cc] = v.w;
            }
            __syncthreads();

            if (act) {
                #pragma unroll 4
                for (int kk = 0; kk < 32; kk++) {
                    float b[10];
                    #pragma unroll
                    for (int j = 0; j < 10; j++) b[j] = sF[kk][tc*10 + j];
                    #pragma unroll
                    for (int i = 0; i < 4; i++) {
                        float a = sX[kk][tr + 16*i];
                        #pragma unroll
                        for (int j = 0; j < 10; j++) acc[i][j] = fmaf(a, b[j], acc[i][j]);
                    }
                }
            }
        }

        if (act) {
            #pragma unroll
            for (int i = 0; i < 4; i++) {
                int r = r0 + tr + 16*i;
                if (r < NN) {
                    float* drow = g_D + (size_t)r * NKT + tc*10;
                    #pragma unroll
                    for (int j = 0; j < 10; j++) drow[j] = acc[i][j];
                }
            }
        }
    } else if (blk == SETUP_BLOCK) {
        if (tid == 0) {
            float a0 = alpha0[0];
            float alpha = 1.0f / (1.0f + __expf(-a0));
            g_consts[0] = 2.0f * alpha / REGc;
            g_consts[1] = 4.0f * alpha / REGc;
            g_consts[2] = (1.0f - alpha) / REGc;
        }
        for (int idx = tid; idx < NKT; idx += 272) {
            const float* row = F2 + (size_t)idx * NF;
            float s = 0.f;
            #pragma unroll 8
            for (int f = 0; f < NF; f++) { float v = row[f]; s += v * v; }
            g_f2n[idx] = s;
        }
    } else {
        const int ln = tid / MM;
        const int i  = tid - ln * MM;
        const int n  = (blk - ADJ_BLOCK0) * NPB + ln;
        const bool ok = (n < NN) && (ln < NPB);

        if (ok) {
            const int* dstn = dst + (size_t)n * DEG;
            int u = (i == 0) ? n : dstn[i - 1];
            g_nbrs[n * MM + i] = u;

            const int* dstu = dst + (size_t)u * DEG;
            int du[DEG];
            #pragma unroll
            for (int e = 0; e < DEG; e++) du[e] = dstu[e];
            int dn[DEG];
            #pragma unroll
            for (int e = 0; e < DEG; e++) dn[e] = dstn[e];

            unsigned bits = 0;
            #pragma unroll
            for (int j = 0; j < MM; j++) {
                int v = (j == 0) ? n : dn[j - 1];
                bool hit = false;
                #pragma unroll
                for (int e = 0; e < DEG; e++) hit |= (du[e] == v);
                bits |= (unsigned)hit << j;
            }
            sB[ln][i] = bits;
        }
        __syncthreads();
        if (ok) {
            unsigned mk = sB[ln][i];
            #pragma unroll
            for (int j = 0; j < MM; j++)
                mk |= ((sB[ln][j] >> i) & 1u) << j;
            g_mask[n * MM + i] = mk;
        }
    }
}

// ---------------- main: warp-synchronous, packed f32x2 ----------------
// block = 1 node, 8 warps; warp = 2 templates x 16 rows (+ distributed row 0)
__global__ void __launch_bounds__(TPB_MAIN, 3)
k_main(const float* __restrict__ C2g, float* __restrict__ out) {
    __shared__ __align__(16) float sT [NT][MM][MTP];
    __shared__ __align__(16) float sW [NT][MM][MTP];
    __shared__ __align__(16) float sC2[NT][MT][MTP];
    __shared__ __align__(16) float sq [NT][MTP];
    __shared__ __align__(16) float sU [NT][MTP];
    __shared__ __align__(16) float sRS [NT][MTP];
    __shared__ __align__(16) float sRS2[NT][MTP];
    __shared__ int sList[NWARPS][32];
    __shared__ int sLn[NWARPS];

    const int tid = threadIdx.x;
    const int n   = blockIdx.x;
    const int w   = tid >> 5;
    const int l   = tid & 31;
    const int g   = l >> 4;            // template within warp
    const int j   = l & 15;            // 0..15
    const int kk  = w * 2 + g;         // global template 0..15
    const int r   = j + 1;             // own row 1..16
    const bool sl = (j < MT);          // s-lane (owns output column j)

    const float cA = g_consts[0];
    const float cY = g_consts[1];
    const float cM = g_consts[2];

    // warp-local C2 load (2 templates)
    for (int idx = l; idx < 2 * MT * MTP; idx += 32) {
        int kkk = w*2 + idx / (MT*MTP);
        int rr  = idx % (MT*MTP);
        int s2  = rr / MTP, t2 = rr % MTP;
        sC2[kkk][s2][t2] = (t2 < MT) ? C2g[(kkk*MT + s2)*MT + t2] : 0.f;
    }

    // negated basec for own row: nb[t] = cM*(2*dot - f2n)  (packed)
    const int u = g_nbrs[n*MM + r];
    u64 nb2[5];
    {
        const float2* drow = (const float2*)(g_D + (size_t)u * NKT + kk * MT);
        const float2* frow = (const float2*)(g_f2n + kk * MT);
        #pragma unroll
        for (int h = 0; h < 5; h++) {
            float2 v = __ldg(drow + h);
            float2 f = frow[h];
            nb2[h] = pk2(cM * (2.0f * v.x - f.x), cM * (2.0f * v.y - f.y));
        }
    }
    // row-0 negated basec element (s-lanes only)
    float nb0 = 0.f;
    if (sl) {
        float d0 = __ldg(g_D + (size_t)n * NKT + kk * MT + j);
        nb0 = cM * (2.0f * d0 - g_f2n[kk * MT + j]);
    }

    // masks
    const unsigned mask = g_mask[n*MM + r];
    const unsigned resmask = mask & ~1u;
    const int nres = __popc(resmask);
    unsigned m0 = 0;
    if (j == 0) m0 = g_mask[n*MM];
    m0 = __shfl_sync(0xffffffffu, m0, 0, 16);
    const float c00 = (m0 & 1u) ? 0.f : -1.f;        // C1[0,0]-1

    // per-half colmask via shuffle-OR
    unsigned cmk = resmask;
    cmk |= __shfl_xor_sync(0xffffffffu, cmk, 1, 16);
    cmk |= __shfl_xor_sync(0xffffffffu, cmk, 2, 16);
    cmk |= __shfl_xor_sync(0xffffffffu, cmk, 4, 16);
    cmk |= __shfl_xor_sync(0xffffffffu, cmk, 8, 16);
    unsigned cmB = __shfl_sync(0xffffffffu, cmk, 16);
    __syncwarp();
    if (l == 0) {
        int L = 0;
        unsigned ca = cmk;
        while (ca) { int b = __ffs(ca)-1; ca &= ca-1; sList[w][L++] = b; }
        unsigned cb = cmB;
        while (cb) { int b = __ffs(cb)-1; cb &= cb-1; sList[w][L++] = 32 | b; }
        sLn[w] = L;
    }
    __syncwarp();
    const int L10 = 10 * sLn[w];
    int offA = 0, offB = 0, offW = 0;
    const bool hasTask = (l < L10);
    if (hasTask) {
        int p = l / 10, s2 = l - p*10;
        int ent = sList[w][p];
        int kt = w*2 + (ent >> 5); int b = ent & 31;
        offA = (kt*MT + s2) * MTP;
        offB = (kt*MM + b) * MTP;
        offW = offB + s2;
    }

    // persistent packed C2 row for s-lanes; rowsums for peel
    u64 cr2[5];
    {
        const float* crp = &sC2[kk][sl ? j : 0][0];
        ulonglong2 c01 = *(const ulonglong2*)crp;
        ulonglong2 c23 = *(const ulonglong2*)(crp + 4);
        cr2[0] = c01.x; cr2[1] = c01.y; cr2[2] = c23.x; cr2[3] = c23.y;
        cr2[4] = *(const u64*)(crp + 8);
    }
    float rsown, rs2own;
    {
        u64 rp = add2(add2(cr2[0], cr2[1]), add2(cr2[2], cr2[3]));
        rp = add2(rp, cr2[4]);
        rsown = hsum2(rp);
        u64 sp = mul2(cr2[0], cr2[0]);
        sp = fma2(cr2[1], cr2[1], sp);
        sp = fma2(cr2[2], cr2[2], sp);
        sp = fma2(cr2[3], cr2[3], sp);
        sp = fma2(cr2[4], cr2[4], sp);
        rs2own = hsum2(sp);
    }
    if (sl) { sRS[kk][j] = rsown; sRS2[kk][j] = rs2own; }
    __syncwarp();

    // ---- peeled iteration 0 (T uniform = 1/170), packed ----
    const float E0 = 1.0f / 170.0f;
    const float g2 = 0.1f * cA;
    u64 lt2[5];
    {
        float cf = cY * (E0 * (1.0f + (float)nres));
        u64 cf2 = pk2(cf, cf);
        u64 ng2 = pk2(-g2, -g2);
        const float* rsp  = &sRS [kk][0];
        const float* rs2p = &sRS2[kk][0];
        ulonglong2 ra = *(const ulonglong2*)rsp;
        ulonglong2 rb = *(const ulonglong2*)(rsp + 4);
        u64 rc = *(const u64*)(rsp + 8);
        ulonglong2 sa = *(const ulonglong2*)rs2p;
        ulonglong2 sb = *(const ulonglong2*)(rs2p + 4);
        u64 sc = *(const u64*)(rs2p + 8);
        lt2[0] = fma2(cf2, ra.x, fma2(ng2, sa.x, nb2[0]));
        lt2[1] = fma2(cf2, ra.y, fma2(ng2, sa.y, nb2[1]));
        lt2[2] = fma2(cf2, rb.x, fma2(ng2, sb.x, nb2[2]));
        lt2[3] = fma2(cf2, rb.y, fma2(ng2, sb.y, nb2[3]));
        lt2[4] = fma2(cf2, rc,   fma2(ng2, sc,   nb2[4]));
    }
    float lt0 = 0.f;
    if (sl) lt0 = cY * (0.1f + c00 * E0) * rsown - g2 * rs2own + nb0;

    float w0own = 0.f;

    #pragma unroll 1
    for (int it = 1; it <= 10; it++) {
        // phase 1: softmax own row + store; distributed row-0 softmax
        {
            float f[MT];
            up2(lt2[0], f[0], f[1]); up2(lt2[1], f[2], f[3]);
            up2(lt2[2], f[4], f[5]); up2(lt2[3], f[6], f[7]);
            up2(lt2[4], f[8], f[9]);
            float mx = f[0];
            #pragma unroll
            for (int t = 1; t < MT; t++) mx = fmaxf(mx, f[t]);
            float e[MT];
            #pragma unroll
            for (int t = 0; t < MT; t++) e[t] = __expf(f[t] - mx);
            u64 e2[5];
            #pragma unroll
            for (int h = 0; h < 5; h++) e2[h] = pk2(e[2*h], e[2*h+1]);
            u64 sp = add2(add2(e2[0], e2[1]), add2(e2[2], e2[3]));
            sp = add2(sp, e2[4]);
            float pr = (1.0f / MM) / hsum2(sp);
            u64 pr2 = pk2(pr, pr);
            #pragma unroll
            for (int h = 0; h < 5; h++) e2[h] = mul2(e2[h], pr2);
            float* Trow = &sT[kk][r][0];
            ulonglong2 st0; st0.x = e2[0]; st0.y = e2[1];
            ulonglong2 st1; st1.x = e2[2]; st1.y = e2[3];
            *(ulonglong2*)Trow = st0;
            *(ulonglong2*)(Trow + 4) = st1;
            *(u64*)(Trow + 8) = e2[4];
        }
        {
            float mx0 = sl ? lt0 : -3.0e38f;
            mx0 = fmaxf(mx0, __shfl_xor_sync(0xffffffffu, mx0, 1, 16));
            mx0 = fmaxf(mx0, __shfl_xor_sync(0xffffffffu, mx0, 2, 16));
            mx0 = fmaxf(mx0, __shfl_xor_sync(0xffffffffu, mx0, 4, 16));
            mx0 = fmaxf(mx0, __shfl_xor_sync(0xffffffffu, mx0, 8, 16));
            float e0 = sl ? __expf(lt0 - mx0) : 0.f;
            float s0 = e0;
            s0 += __shfl_xor_sync(0xffffffffu, s0, 1, 16);
            s0 += __shfl_xor_sync(0xffffffffu, s0, 2, 16);
            s0 += __shfl_xor_sync(0xffffffffu, s0, 4, 16);
            s0 += __shfl_xor_sync(0xffffffffu, s0, 8, 16);
            if (sl) sT[kk][0][j] = e0 * ((1.0f / MM) / s0);
        }
        __syncwarp();

        if (it == 10) break;   // final T stored; epilogue computes q

        // phase 2: colsum + W0 (s-lanes); worklist dots (all lanes)
        if (sl) {
            float qv = 0.f;
            #pragma unroll
            for (int b = 0; b < MM; b++) qv += sT[kk][b][j];
            sq[kk][j] = qv;

            const float* t0p = &sT[kk][0][0];
            ulonglong2 t01 = *(const ulonglong2*)t0p;
            ulonglong2 t23 = *(const ulonglong2*)(t0p + 4);
            u64 t4 = *(const u64*)(t0p + 8);
            u64 wp = mul2(cr2[0], t01.x);
            wp = fma2(cr2[1], t01.y, wp);
            wp = fma2(cr2[2], t23.x, wp);
            wp = fma2(cr2[3], t23.y, wp);
            wp = fma2(cr2[4], t4,   wp);
            w0own = hsum2(wp);
        }
        if (hasTask)
            ((float*)sW)[offW] = cY * dot10p(&((const float*)sC2)[offA],
                                            &((const float*)sT)[offB]);
        for (int idx = l + 32; idx < L10; idx += 32) {
            int p = idx / 10, s2 = idx - p*10;
            int ent = sList[w][p];
            int kt = w*2 + (ent >> 5); int b = ent & 31;
            sW[kt][b][s2] = cY * dot10p(&sC2[kt][s2][0], &sT[kt][b][0]);
        }
        __syncwarp();

        // phase 3: s-lanes: packed Zq/cc; publish U; update row-0 logit
        if (sl) {
            const float* qp = &sq[kk][0];
            ulonglong2 q01 = *(const ulonglong2*)qp;
            ulonglong2 q23 = *(const ulonglong2*)(qp + 4);
            u64 q4 = *(const u64*)(qp + 8);
            u64 t0 = mul2(cr2[0], q01.x);
            u64 t1 = mul2(cr2[1], q01.y);
            u64 t2 = mul2(cr2[2], q23.x);
            u64 t3 = mul2(cr2[3], q23.y);
            u64 t4 = mul2(cr2[4], q4);
            u64 zp = add2(add2(t0, t1), add2(t2, t3));
            zp = add2(zp, t4);
            u64 cp = mul2(t0, cr2[0]);
            cp = fma2(t1, cr2[1], cp);
            cp = fma2(t2, cr2[2], cp);
            cp = fma2(t3, cr2[3], cp);
            cp = fma2(t4, cr2[4], cp);
            float zq = hsum2(zp);
            float gcs = cA * hsum2(cp);
            sU[kk][j] = cY * w0own - gcs;
            lt0 += cY * fmaf(c00, w0own, zq) - gcs + nb0;
        }
        __syncwarp();

        // phase 4: all lanes packed update: lt += U + nb (+ residual rows)
        {
            const float* Ur = &sU[kk][0];
            ulonglong2 u01 = *(const ulonglong2*)Ur;
            ulonglong2 u23 = *(const ulonglong2*)(Ur + 4);
            u64 u4 = *(const u64*)(Ur + 8);
            lt2[0] = add2(lt2[0], add2(u01.x, nb2[0]));
            lt2[1] = add2(lt2[1], add2(u01.y, nb2[1]));
            lt2[2] = add2(lt2[2], add2(u23.x, nb2[2]));
            lt2[3] = add2(lt2[3], add2(u23.y, nb2[3]));
            lt2[4] = add2(lt2[4], add2(u4,    nb2[4]));

            unsigned rm = resmask;
            while (rm) {
                int b = __ffs(rm) - 1; rm &= rm - 1;
                const float* Wr = &sW[kk][b][0];
                ulonglong2 w01 = *(const ulonglong2*)Wr;
                ulonglong2 w23 = *(const ulonglong2*)(Wr + 4);
                u64 w4 = *(const u64*)(Wr + 8);
                lt2[0] = add2(lt2[0], w01.x);
                lt2[1] = add2(lt2[1], w01.y);
                lt2[2] = add2(lt2[2], w23.x);
                lt2[3] = add2(lt2[3], w23.y);
                lt2[4] = add2(lt2[4], w4);
            }
        }
    }

    // epilogue: final marginal q (T already stored at it==10)
    if (sl) {
        float qv = 0.f;
        #pragma unroll
        for (int b = 0; b < MM; b++) qv += sT[kk][b][j];
        out[(size_t)n * NKT + kk * MT + j] = qv;
    }
}

// ---------------- launch ----------------
extern "C" void kernel_launch(void* const* d_in, const int* in_sizes, int n_in,
                              void* d_out, int out_size) {
    const float* x      = (const float*)d_in[0];
    const int*   eidx   = (const int*)d_in[1];
    const float* C2g    = (const float*)d_in[2];
    const float* F2     = (const float*)d_in[3];
    const float* alpha0 = (const float*)d_in[4];
    float* out = (float*)d_out;

    const int* dst = eidx + NN * DEG;   // row 1 of edge_index

    k_prep<<<PREP_BLOCKS, 272>>>(x, F2, alpha0, dst);
    k_main<<<NN, TPB_MAIN>>>(C2g, out);
}